// round 8
// baseline (speedup 1.0000x reference)
#include <cuda_runtime.h>
#include <cuda_bf16.h>
#include <stdint.h>
#include <math.h>

#define DM     1024
#define HEADS  16
#define DKH    64
#define BATCH  2
#define SEQ    2048
#define MTOT   (BATCH*SEQ)
#define GK     3072            // split-bf16 concatenated K (projections)

// ---------------- scratch (static device globals) --------------------------
__device__ uint4 g_abig[(size_t)MTOT * GK * 2 / 16];      // bf16 [4096][3072]
__device__ uint4 g_wbig[(size_t)4 * DM * GK * 2 / 16];    // 4 x bf16 [1024][3072]
__device__ uint4 g_cbig[(size_t)MTOT * GK * 2 / 16];      // bf16 [4096][3072]
__device__ float g_q[(size_t)MTOT * DM];                  // fp32 [m][1024]
__device__ float g_k[(size_t)MTOT * DM];
__device__ float g_v[(size_t)MTOT * DM];
__device__ float g_ctx[(size_t)MTOT * DM];
// attention operands
__device__ uint4 g_qs[(size_t)32 * SEQ * 192 * 2 / 16];   // bf16 [bh][s][192] (hi,hi,lo)
__device__ uint4 g_ks[(size_t)32 * SEQ * 192 * 2 / 16];   // bf16 [bh][s][192] (hi,lo,hi)
__device__ uint4 g_vt[(size_t)32 * 2 * DKH * SEQ * 2 / 16]; // bf16 [bh][seg][d][s]
__device__ uint32_t g_mbits[(size_t)BATCH * SEQ * SEQ / 32]; // packed mask bits

// ---------------- small helpers --------------------------------------------
__device__ __forceinline__ uint32_t smem_u32(const void* p) {
    uint32_t a;
    asm("{ .reg .u64 t; cvta.to.shared.u64 t, %1; cvt.u32.u64 %0, t; }" : "=r"(a) : "l"(p));
    return a;
}
__device__ __forceinline__ void cpa16(uint32_t s, const void* g) {
    asm volatile("cp.async.cg.shared.global [%0], [%1], 16;" :: "r"(s), "l"(g));
}
#define CPA_COMMIT() asm volatile("cp.async.commit_group;" ::: "memory")
#define CPA_WAIT(N)  asm volatile("cp.async.wait_group %0;" :: "n"(N) : "memory")

__device__ __forceinline__ void ldsm4(uint32_t& r0, uint32_t& r1, uint32_t& r2, uint32_t& r3,
                                      uint32_t addr) {
    asm volatile("ldmatrix.sync.aligned.m8n8.x4.shared.b16 {%0,%1,%2,%3}, [%4];"
                 : "=r"(r0), "=r"(r1), "=r"(r2), "=r"(r3) : "r"(addr));
}
__device__ __forceinline__ void mma16816(float& d0, float& d1, float& d2, float& d3,
                                         uint32_t a0, uint32_t a1, uint32_t a2, uint32_t a3,
                                         uint32_t b0, uint32_t b1) {
    asm volatile("mma.sync.aligned.m16n8k16.row.col.f32.bf16.bf16.f32 "
                 "{%0,%1,%2,%3}, {%4,%5,%6,%7}, {%8,%9}, {%0,%1,%2,%3};"
                 : "+f"(d0), "+f"(d1), "+f"(d2), "+f"(d3)
                 : "r"(a0), "r"(a1), "r"(a2), "r"(a3), "r"(b0), "r"(b1));
}

// ---------------------------------------------------------------------------
// mask_pack: int32 mask [b][sq][sk] -> bit per element (1 = keep)
// ---------------------------------------------------------------------------
__global__ __launch_bounds__(256)
void mask_pack(const int* __restrict__ mask, uint32_t* __restrict__ bits)
{
    const size_t tid = (size_t)blockIdx.x * 256 + threadIdx.x;
    const int lane = threadIdx.x & 31;
    const int mv = mask[tid];
    const uint32_t w = __ballot_sync(0xffffffffu, mv != 0);
    if (lane == 0) bits[tid >> 5] = w;
}

// ---------------------------------------------------------------------------
// split: X fp32 [rows][1024] -> Y bf16 [rows][3072]
// SIDE 0 (A operand): (hi,hi,lo);  SIDE 1 (B): (hi,lo,hi)
// ---------------------------------------------------------------------------
template<int SIDE>
__global__ __launch_bounds__(256)
void split_kernel(const float* __restrict__ X, __nv_bfloat16* __restrict__ Y)
{
    const int idx = blockIdx.x * 256 + threadIdx.x;
    const int r   = idx >> 8;
    const int c4  = (idx & 255) * 4;
    const float4 x = *(const float4*)(X + (size_t)r * DM + c4);

    __nv_bfloat16 h0 = __float2bfloat16(x.x), h1 = __float2bfloat16(x.y);
    __nv_bfloat16 h2 = __float2bfloat16(x.z), h3 = __float2bfloat16(x.w);
    __nv_bfloat16 l0 = __float2bfloat16(x.x - __bfloat162float(h0));
    __nv_bfloat16 l1 = __float2bfloat16(x.y - __bfloat162float(h1));
    __nv_bfloat16 l2 = __float2bfloat16(x.z - __bfloat162float(h2));
    __nv_bfloat16 l3 = __float2bfloat16(x.w - __bfloat162float(h3));

    __nv_bfloat162 hA = __halves2bfloat162(h0,h1), hB = __halves2bfloat162(h2,h3);
    __nv_bfloat162 lA = __halves2bfloat162(l0,l1), lB = __halves2bfloat162(l2,l3);

    __nv_bfloat162* y0 = (__nv_bfloat162*)(Y + (size_t)r * GK + c4);
    __nv_bfloat162* y1 = (__nv_bfloat162*)(Y + (size_t)r * GK + 1024 + c4);
    __nv_bfloat162* y2 = (__nv_bfloat162*)(Y + (size_t)r * GK + 2048 + c4);
    y0[0] = hA; y0[1] = hB;
    if (SIDE == 0) { y1[0] = hA; y1[1] = hB; y2[0] = lA; y2[1] = lB; }
    else           { y1[0] = lA; y1[1] = lB; y2[0] = hA; y2[1] = hB; }
}

// ---------------------------------------------------------------------------
// HMMA GEMM (unchanged — known good)
// ---------------------------------------------------------------------------
#define ROWB   80
#define TILEB  (128*ROWB)
#define HS_A0  0
#define HS_B0  TILEB
#define HS_A1  (2*TILEB)
#define HS_B1  (3*TILEB)
#define HSMEM  (4*TILEB)

__global__ __launch_bounds__(256, 2)
void hgemm(const __nv_bfloat16* __restrict__ A, const __nv_bfloat16* __restrict__ B,
           const float* __restrict__ bias, float* __restrict__ out)
{
    extern __shared__ char sm[];
    const uint32_t sbase = smem_u32(sm);
    const int tid  = threadIdx.x;
    const int m0   = blockIdx.x * 128;
    const int n0   = blockIdx.y * 128;

    const int r0c = tid >> 2,  c0c = tid & 3;
    const int r1c = r0c + 64;
    const __nv_bfloat16* Ag0 = A + (size_t)(m0 + r0c) * GK + c0c * 8;
    const __nv_bfloat16* Ag1 = A + (size_t)(m0 + r1c) * GK + c0c * 8;
    const __nv_bfloat16* Bg0 = B + (size_t)(n0 + r0c) * GK + c0c * 8;
    const __nv_bfloat16* Bg1 = B + (size_t)(n0 + r1c) * GK + c0c * 8;
    const uint32_t sA_off0 = r0c * ROWB + c0c * 16;
    const uint32_t sA_off1 = r1c * ROWB + c0c * 16;

    const uint32_t abuf[2] = { sbase + HS_A0, sbase + HS_A1 };
    const uint32_t bbuf[2] = { sbase + HS_B0, sbase + HS_B1 };

    const int wid  = tid >> 5, lane = tid & 31;
    const int wm   = (wid >> 2) * 64;
    const int wn   = (wid & 3) * 32;

    const uint32_t aoff = (uint32_t)(wm + (lane & 15)) * ROWB + (lane >> 4) * 16;
    const uint32_t boff = (uint32_t)(wn + ((lane >> 4) & 1) * 8 + (lane & 7)) * ROWB
                        + ((lane >> 3) & 1) * 16;

    float acc[4][4][4] = {};

    #define LOAD_TILE(it, buf) do {                                            \
        const size_t kb = (size_t)(it) * 32;                                   \
        cpa16(abuf[buf] + sA_off0, Ag0 + kb);                                  \
        cpa16(abuf[buf] + sA_off1, Ag1 + kb);                                  \
        cpa16(bbuf[buf] + sA_off0, Bg0 + kb);                                  \
        cpa16(bbuf[buf] + sA_off1, Bg1 + kb);                                  \
        CPA_COMMIT();                                                          \
    } while (0)

    LOAD_TILE(0, 0);

    const int KITERS = GK / 32;
    for (int it = 0; it < KITERS; it++) {
        const int cur = it & 1;
        if (it + 1 < KITERS) { LOAD_TILE(it + 1, cur ^ 1); CPA_WAIT(1); }
        else                 { CPA_WAIT(0); }
        __syncthreads();

        #pragma unroll
        for (int kk = 0; kk < 2; kk++) {
            const uint32_t kb = kk * 32;
            uint32_t a[4][4], b[4][2];
            #pragma unroll
            for (int mt = 0; mt < 4; mt++)
                ldsm4(a[mt][0], a[mt][1], a[mt][2], a[mt][3],
                      abuf[cur] + aoff + (uint32_t)mt * (16*ROWB) + kb);
            #pragma unroll
            for (int np = 0; np < 2; np++) {
                uint32_t q0,q1,q2,q3;
                ldsm4(q0,q1,q2,q3, bbuf[cur] + boff + (uint32_t)np * (16*ROWB) + kb);
                b[np*2+0][0] = q0; b[np*2+0][1] = q1;
                b[np*2+1][0] = q2; b[np*2+1][1] = q3;
            }
            #pragma unroll
            for (int mt = 0; mt < 4; mt++)
                #pragma unroll
                for (int nt = 0; nt < 4; nt++)
                    mma16816(acc[mt][nt][0], acc[mt][nt][1], acc[mt][nt][2], acc[mt][nt][3],
                             a[mt][0], a[mt][1], a[mt][2], a[mt][3],
                             b[nt][0], b[nt][1]);
        }
        __syncthreads();
    }

    const int erow = lane >> 2;
    const int ecol = (lane & 3) * 2;
    #pragma unroll
    for (int nt = 0; nt < 4; nt++) {
        const int col = n0 + wn + nt * 8 + ecol;
        const float2 bv = *(const float2*)(bias + col);
        #pragma unroll
        for (int mt = 0; mt < 4; mt++) {
            const int m = m0 + wm + mt * 16 + erow;
            float2 w0, w1;
            w0.x = acc[mt][nt][0] + bv.x; w0.y = acc[mt][nt][1] + bv.y;
            w1.x = acc[mt][nt][2] + bv.x; w1.y = acc[mt][nt][3] + bv.y;
            *(float2*)(out + (size_t)m * DM + col)       = w0;
            *(float2*)(out + (size_t)(m + 8) * DM + col) = w1;
        }
    }
    #undef LOAD_TILE
}

// ---------------------------------------------------------------------------
// qk_split: fp32 [m][1024] -> per-head split bf16 [bh][s][192]
// SIDE 0 = Q (hi,hi,lo), SIDE 1 = K (hi,lo,hi)
// ---------------------------------------------------------------------------
template<int SIDE>
__global__ __launch_bounds__(256)
void qk_split(const float* __restrict__ X, __nv_bfloat16* __restrict__ Y)
{
    const int m = blockIdx.x;
    const int b = m >> 11, s = m & (SEQ-1);
    const int t = threadIdx.x;
    const int col = t * 4;
    const int h = col >> 6;
    const int d = col & 63;
    const float4 x = *(const float4*)(X + (size_t)m * DM + col);

    __nv_bfloat16 h0 = __float2bfloat16(x.x), h1 = __float2bfloat16(x.y);
    __nv_bfloat16 h2 = __float2bfloat16(x.z), h3 = __float2bfloat16(x.w);
    __nv_bfloat16 l0 = __float2bfloat16(x.x - __bfloat162float(h0));
    __nv_bfloat16 l1 = __float2bfloat16(x.y - __bfloat162float(h1));
    __nv_bfloat16 l2 = __float2bfloat16(x.z - __bfloat162float(h2));
    __nv_bfloat16 l3 = __float2bfloat16(x.w - __bfloat162float(h3));

    __nv_bfloat162 hA = __halves2bfloat162(h0,h1), hB = __halves2bfloat162(h2,h3);
    __nv_bfloat162 lA = __halves2bfloat162(l0,l1), lB = __halves2bfloat162(l2,l3);

    __nv_bfloat16* base = Y + ((size_t)(b*HEADS + h) * SEQ + s) * 192;
    __nv_bfloat162* y0 = (__nv_bfloat162*)(base + d);
    __nv_bfloat162* y1 = (__nv_bfloat162*)(base + 64 + d);
    __nv_bfloat162* y2 = (__nv_bfloat162*)(base + 128 + d);
    y0[0] = hA; y0[1] = hB;
    if (SIDE == 0) { y1[0] = hA; y1[1] = hB; y2[0] = lA; y2[1] = lB; }
    else           { y1[0] = lA; y1[1] = lB; y2[0] = hA; y2[1] = hB; }
}

// ---------------------------------------------------------------------------
// v_split: fp32 [m][1024] -> bf16 transposed [bh][seg][d=64][s=2048]
// ---------------------------------------------------------------------------
__global__ __launch_bounds__(256)
void v_split(const float* __restrict__ V, __nv_bfloat16* __restrict__ Y)
{
    __shared__ float sm[64][132];
    const int bh = blockIdx.y;
    const int b = bh >> 4, h = bh & 15;
    const int sblk = blockIdx.x * 128;
    const int t = threadIdx.x;

    {
        const int srow = t >> 1, half = (t & 1) * 32;
        const float* src = V + ((size_t)b * SEQ + sblk + srow) * DM + h * DKH + half;
        #pragma unroll
        for (int j = 0; j < 8; j++) {
            const float4 v = *(const float4*)(src + j*4);
            sm[half + j*4 + 0][srow] = v.x;
            sm[half + j*4 + 1][srow] = v.y;
            sm[half + j*4 + 2][srow] = v.z;
            sm[half + j*4 + 3][srow] = v.w;
        }
    }
    __syncthreads();
    {
        const int d = t >> 2, sc = (t & 3) * 32;
        __nv_bfloat162* dh = (__nv_bfloat162*)(Y + (((size_t)bh*2 + 0) * DKH + d) * SEQ + sblk + sc);
        __nv_bfloat162* dl = (__nv_bfloat162*)(Y + (((size_t)bh*2 + 1) * DKH + d) * SEQ + sblk + sc);
        #pragma unroll
        for (int j = 0; j < 16; j++) {
            const float a = sm[d][sc + j*2], c = sm[d][sc + j*2 + 1];
            __nv_bfloat16 ha = __float2bfloat16(a), hc = __float2bfloat16(c);
            __nv_bfloat16 la = __float2bfloat16(a - __bfloat162float(ha));
            __nv_bfloat16 lc = __float2bfloat16(c - __bfloat162float(hc));
            dh[j] = __halves2bfloat162(ha, hc);
            dl[j] = __halves2bfloat162(la, lc);
        }
    }
}

// ---------------------------------------------------------------------------
// HMMA flash attention: 64 q-rows/CTA, 4 warps, single-buffered K/V,
// 2 CTAs/SM for cross-CTA overlap. Bit-packed mask, exp2 softmax.
// smem: Qs [64][400B] | K [128][400B] | V [2][64][272B]  = 111616 B
// ---------------------------------------------------------------------------
#define QROWB 400
#define VROWB 272
#define AS_Q  0
#define AS_K  25600
#define AS_V  76800
#define ASMEM 111616
#define LOG2E_8TH 0.1803368801111204f   // 0.125 * log2(e)

__global__ __launch_bounds__(128, 2)
void attn_mma(const __nv_bfloat16* __restrict__ Qs, const __nv_bfloat16* __restrict__ Ks,
              const __nv_bfloat16* __restrict__ Vt, const uint32_t* __restrict__ mbits,
              float* __restrict__ ctx)
{
    extern __shared__ char sm[];
    const uint32_t sb = smem_u32(sm);
    const int tid  = threadIdx.x;
    const int lane = tid & 31;
    const int wm   = (tid >> 5) * 16;            // 4 warps x 16 rows
    const int bh   = blockIdx.y;
    const int b    = bh >> 4, h = bh & 15;
    const int q0g  = blockIdx.x * 64;

    const __nv_bfloat16* qb = Qs + ((size_t)bh * SEQ + q0g) * 192;
    const __nv_bfloat16* kb = Ks + (size_t)bh * SEQ * 192;
    const __nv_bfloat16* vb = Vt + (size_t)bh * 2 * DKH * SEQ;

    // Q tile once: 64 rows, 128 threads -> half row each
    {
        const int lrow = tid >> 1, lhalf = tid & 1;
        const uint32_t sq = sb + AS_Q + lrow * QROWB + lhalf * 192;
        const __nv_bfloat16* gq = qb + (size_t)lrow * 192 + lhalf * 96;
        #pragma unroll
        for (int j = 0; j < 12; j++) cpa16(sq + j*16, gq + j*8);
        CPA_COMMIT();
    }

    const uint32_t aoffQ = sb + AS_Q + (uint32_t)(wm + (lane & 15)) * QROWB + (lane >> 4) * 16;
    const uint32_t boffK = sb + AS_K + (uint32_t)(((lane >> 4) & 1) * 8 + (lane & 7)) * QROWB
                         + ((lane >> 3) & 1) * 16;
    const uint32_t boffV = sb + AS_V + (uint32_t)(((lane >> 4) & 1) * 8 + (lane & 7)) * VROWB
                         + ((lane >> 3) & 1) * 16;

    const int r0 = lane >> 2;
    const int cql = (lane & 3) * 2;

    const uint32_t* mrow0 = mbits + ((size_t)b * SEQ + (q0g + wm + r0)) * (SEQ/32);
    const uint32_t* mrow1 = mrow0 + 8 * (SEQ/32);

    float o[8][4] = {};
    float m0 = -1e30f, m1 = -1e30f, l0 = 0.f, l1 = 0.f;

    for (int it = 0; it < SEQ/128; it++) {
        const int kb0 = it * 128;

        // prefetch mask words (independent of staged data)
        const uint4 mq0 = *(const uint4*)(mrow0 + (kb0 >> 5));
        const uint4 mq1 = *(const uint4*)(mrow1 + (kb0 >> 5));

        // stage K (128 rows x 384B) + V (2 seg x 64 rows x 256B), 128 threads
        {
            const uint32_t sk = sb + AS_K + tid * QROWB;
            const __nv_bfloat16* gk = kb + (size_t)(kb0 + tid) * 192;
            #pragma unroll
            for (int j = 0; j < 24; j++) cpa16(sk + j*16, gk + j*8);
            const int seg = tid >> 6, vrow = tid & 63;
            const uint32_t sv = sb + AS_V + seg * (64*VROWB) + vrow * VROWB;
            const __nv_bfloat16* gv = vb + ((size_t)seg * DKH + vrow) * SEQ + kb0;
            #pragma unroll
            for (int j = 0; j < 16; j++) cpa16(sv + j*16, gv + j*8);
            CPA_COMMIT();
        }
        CPA_WAIT(0);
        __syncthreads();

        // ---- S = Q K^T ----
        float s[16][4] = {};
        #pragma unroll
        for (int kk = 0; kk < 12; kk++) {
            uint32_t a0,a1,a2,a3;
            ldsm4(a0,a1,a2,a3, aoffQ + kk*32);
            #pragma unroll
            for (int np = 0; np < 8; np++) {
                uint32_t q0,q1,q2,q3;
                ldsm4(q0,q1,q2,q3, boffK + (uint32_t)np * (16*QROWB) + kk*32);
                mma16816(s[2*np][0], s[2*np][1], s[2*np][2], s[2*np][3], a0,a1,a2,a3, q0,q1);
                mma16816(s[2*np+1][0], s[2*np+1][1], s[2*np+1][2], s[2*np+1][3], a0,a1,a2,a3, q2,q3);
            }
        }

        // ---- mask + scale(in log2 units) + row max ----
        const uint32_t w0[4] = { mq0.x, mq0.y, mq0.z, mq0.w };
        const uint32_t w1[4] = { mq1.x, mq1.y, mq1.z, mq1.w };
        float mx0 = -1e30f, mx1 = -1e30f;
        #pragma unroll
        for (int t = 0; t < 16; t++) {
            const int sh = (t & 3) * 8 + cql;
            const uint32_t a = w0[t >> 2] >> sh;
            const uint32_t c = w1[t >> 2] >> sh;
            s[t][0] = (a & 1u) ? s[t][0] * LOG2E_8TH : -1e9f;
            s[t][1] = (a & 2u) ? s[t][1] * LOG2E_8TH : -1e9f;
            s[t][2] = (c & 1u) ? s[t][2] * LOG2E_8TH : -1e9f;
            s[t][3] = (c & 2u) ? s[t][3] * LOG2E_8TH : -1e9f;
            mx0 = fmaxf(mx0, fmaxf(s[t][0], s[t][1]));
            mx1 = fmaxf(mx1, fmaxf(s[t][2], s[t][3]));
        }
        mx0 = fmaxf(mx0, __shfl_xor_sync(0xffffffffu, mx0, 1));
        mx0 = fmaxf(mx0, __shfl_xor_sync(0xffffffffu, mx0, 2));
        mx1 = fmaxf(mx1, __shfl_xor_sync(0xffffffffu, mx1, 1));
        mx1 = fmaxf(mx1, __shfl_xor_sync(0xffffffffu, mx1, 2));

        const float nm0 = fmaxf(m0, mx0), nm1 = fmaxf(m1, mx1);
        const float c0 = exp2f(m0 - nm0), c1 = exp2f(m1 - nm1);
        m0 = nm0; m1 = nm1;

        // ---- exp2, row-sum, pack P hi/lo fragments ----
        uint32_t php[16][2], plp[16][2];
        float rs0 = 0.f, rs1 = 0.f;
        #pragma unroll
        for (int t = 0; t < 16; t++) {
            float p0 = exp2f(s[t][0] - nm0);
            float p1 = exp2f(s[t][1] - nm0);
            float p2 = exp2f(s[t][2] - nm1);
            float p3 = exp2f(s[t][3] - nm1);
            rs0 += p0 + p1; rs1 += p2 + p3;
            __nv_bfloat16 h0 = __float2bfloat16(p0), h1 = __float2bfloat16(p1);
            __nv_bfloat16 h2 = __float2bfloat16(p2), h3 = __float2bfloat16(p3);
            __nv_bfloat162 ph0 = __halves2bfloat162(h0, h1);
            __nv_bfloat162 ph1 = __halves2bfloat162(h2, h3);
            php[t][0] = *(uint32_t*)&ph0;
            php[t][1] = *(uint32_t*)&ph1;
            __nv_bfloat162 pl0 = __floats2bfloat162_rn(p0 - __bfloat162float(h0),
                                                       p1 - __bfloat162float(h1));
            __nv_bfloat162 pl1 = __floats2bfloat162_rn(p2 - __bfloat162float(h2),
                                                       p3 - __bfloat162float(h3));
            plp[t][0] = *(uint32_t*)&pl0;
            plp[t][1] = *(uint32_t*)&pl1;
        }
        rs0 += __shfl_xor_sync(0xffffffffu, rs0, 1);
        rs0 += __shfl_xor_sync(0xffffffffu, rs0, 2);
        rs1 += __shfl_xor_sync(0xffffffffu, rs1, 1);
        rs1 += __shfl_xor_sync(0xffffffffu, rs1, 2);
        l0 = l0 * c0 + rs0;
        l1 = l1 * c1 + rs1;

        #pragma unroll
        for (int nt = 0; nt < 8; nt++) {
            o[nt][0] *= c0; o[nt][1] *= c0;
            o[nt][2] *= c1; o[nt][3] *= c1;
        }

        // ---- O += Ph*Vh + Ph*Vl + Pl*Vh ----
        #pragma unroll
        for (int pass = 0; pass < 3; pass++) {
            const uint32_t vseg = (pass == 1) ? (uint32_t)(64*VROWB) : 0u;
            #pragma unroll
            for (int j = 0; j < 8; j++) {
                uint32_t a0, a1, a2, a3;
                if (pass == 2) { a0 = plp[2*j][0]; a1 = plp[2*j][1]; a2 = plp[2*j+1][0]; a3 = plp[2*j+1][1]; }
                else           { a0 = php[2*j][0]; a1 = php[2*j][1]; a2 = php[2*j+1][0]; a3 = php[2*j+1][1]; }
                #pragma unroll
                for (int np = 0; np < 4; np++) {
                    uint32_t q0,q1,q2,q3;
                    ldsm4(q0,q1,q2,q3, boffV + vseg + (uint32_t)np * (16*VROWB) + j*32);
                    mma16816(o[2*np][0], o[2*np][1], o[2*np][2], o[2*np][3], a0,a1,a2,a3, q0,q1);
                    mma16816(o[2*np+1][0], o[2*np+1][1], o[2*np+1][2], o[2*np+1][3], a0,a1,a2,a3, q2,q3);
                }
            }
        }
        __syncthreads();   // all reads done before restaging
    }

    // ---- normalize & write ----
    const float i0 = 1.f / l0, i1 = 1.f / l1;
    const int row0 = q0g + wm + r0;
    float* d0 = ctx + ((size_t)b * SEQ + row0) * DM + h * DKH;
    float* d1 = ctx + ((size_t)b * SEQ + row0 + 8) * DM + h * DKH;
    #pragma unroll
    for (int nt = 0; nt < 8; nt++) {
        const int col = nt * 8 + cql;
        float2 v0, v1;
        v0.x = o[nt][0] * i0; v0.y = o[nt][1] * i0;
        v1.x = o[nt][2] * i1; v1.y = o[nt][3] * i1;
        *(float2*)(d0 + col) = v0;
        *(float2*)(d1 + col) = v1;
    }
}

// ---------------------------------------------------------------------------
extern "C" void kernel_launch(void* const* d_in, const int* in_sizes, int n_in,
                              void* d_out, int out_size)
{
    (void)in_sizes; (void)n_in; (void)out_size;
    const float* hid  = (const float*)d_in[0];
    const int*   mask = (const int*)  d_in[1];
    const float* Wq   = (const float*)d_in[2];
    const float* bq   = (const float*)d_in[3];
    const float* Wk   = (const float*)d_in[4];
    const float* bk   = (const float*)d_in[5];
    const float* Wv   = (const float*)d_in[6];
    const float* bv   = (const float*)d_in[7];
    const float* Wo   = (const float*)d_in[8];
    const float* bo   = (const float*)d_in[9];
    float* out = (float*)d_out;

    uint4 *ab, *wb, *cb, *qs, *ks, *vt;
    float *qp, *kp, *vp, *cp;
    uint32_t* mbp;
    cudaGetSymbolAddress((void**)&ab, g_abig);
    cudaGetSymbolAddress((void**)&wb, g_wbig);
    cudaGetSymbolAddress((void**)&cb, g_cbig);
    cudaGetSymbolAddress((void**)&qs, g_qs);
    cudaGetSymbolAddress((void**)&ks, g_ks);
    cudaGetSymbolAddress((void**)&vt, g_vt);
    cudaGetSymbolAddress((void**)&qp, g_q);
    cudaGetSymbolAddress((void**)&kp, g_k);
    cudaGetSymbolAddress((void**)&vp, g_v);
    cudaGetSymbolAddress((void**)&cp, g_ctx);
    cudaGetSymbolAddress((void**)&mbp, g_mbits);

    const size_t WOFF = (size_t)DM * GK / 8;

    cudaFuncSetAttribute(attn_mma, cudaFuncAttributeMaxDynamicSharedMemorySize, ASMEM);

    mask_pack<<<(size_t)BATCH*SEQ*SEQ/256, 256>>>(mask, mbp);

    split_kernel<0><<<MTOT, 256>>>(hid, (__nv_bfloat16*)ab);
    split_kernel<1><<<DM, 256>>>(Wq, (__nv_bfloat16*)(wb + 0*WOFF));
    split_kernel<1><<<DM, 256>>>(Wk, (__nv_bfloat16*)(wb + 1*WOFF));
    split_kernel<1><<<DM, 256>>>(Wv, (__nv_bfloat16*)(wb + 2*WOFF));
    split_kernel<1><<<DM, 256>>>(Wo, (__nv_bfloat16*)(wb + 3*WOFF));

    const dim3 gg(MTOT/128, DM/128);
    hgemm<<<gg, 256, HSMEM>>>((const __nv_bfloat16*)ab, (const __nv_bfloat16*)(wb + 0*WOFF), bq, qp);
    hgemm<<<gg, 256, HSMEM>>>((const __nv_bfloat16*)ab, (const __nv_bfloat16*)(wb + 1*WOFF), bk, kp);
    hgemm<<<gg, 256, HSMEM>>>((const __nv_bfloat16*)ab, (const __nv_bfloat16*)(wb + 2*WOFF), bv, vp);

    qk_split<0><<<MTOT, 256>>>(qp, (__nv_bfloat16*)qs);
    qk_split<1><<<MTOT, 256>>>(kp, (__nv_bfloat16*)ks);
    v_split<<<dim3(SEQ/128, BATCH*HEADS), 256>>>(vp, (__nv_bfloat16*)vt);

    attn_mma<<<dim3(SEQ/64, BATCH*HEADS), 128, ASMEM>>>(
        (const __nv_bfloat16*)qs, (const __nv_bfloat16*)ks,
        (const __nv_bfloat16*)vt, mbp, cp);

    split_kernel<0><<<MTOT, 256>>>(cp, (__nv_bfloat16*)cb);
    hgemm<<<gg, 256, HSMEM>>>((const __nv_bfloat16*)cb, (const __nv_bfloat16*)(wb + 3*WOFF), bo, out);
}

// round 10
// speedup vs baseline: 1.1162x; 1.1162x over previous
#include <cuda_runtime.h>
#include <cuda_bf16.h>
#include <stdint.h>
#include <math.h>

#define DM     1024
#define HEADS  16
#define DKH    64
#define BATCH  2
#define SEQ    2048
#define MTOT   (BATCH*SEQ)
#define GK     3072            // split-bf16 concatenated K (projections)

// ---------------- scratch (static device globals) --------------------------
__device__ uint4 g_abig[(size_t)MTOT * GK * 2 / 16];      // bf16 [4096][3072]
__device__ uint4 g_wbig[(size_t)4 * DM * GK * 2 / 16];    // 4 x bf16 [1024][3072]
__device__ uint4 g_cbig[(size_t)MTOT * GK * 2 / 16];      // bf16 [4096][3072] (split ctx)
__device__ float g_v[(size_t)MTOT * DM];                  // fp32 V [m][1024]
// attention operands
__device__ uint4 g_qs[(size_t)32 * SEQ * 192 * 2 / 16];   // bf16 [bh][s][192] (hi,hi,lo)
__device__ uint4 g_ks[(size_t)32 * SEQ * 192 * 2 / 16];   // bf16 [bh][s][192] (hi,lo,hi)
__device__ uint4 g_vt[(size_t)32 * 2 * DKH * SEQ * 2 / 16]; // bf16 [bh][seg][d][s]
__device__ uint32_t g_mbits[(size_t)BATCH * SEQ * SEQ / 32]; // packed mask bits

// ---------------- small helpers --------------------------------------------
__device__ __forceinline__ uint32_t smem_u32(const void* p) {
    uint32_t a;
    asm("{ .reg .u64 t; cvta.to.shared.u64 t, %1; cvt.u32.u64 %0, t; }" : "=r"(a) : "l"(p));
    return a;
}
__device__ __forceinline__ void cpa16(uint32_t s, const void* g) {
    asm volatile("cp.async.cg.shared.global [%0], [%1], 16;" :: "r"(s), "l"(g));
}
#define CPA_COMMIT() asm volatile("cp.async.commit_group;" ::: "memory")
#define CPA_WAIT(N)  asm volatile("cp.async.wait_group %0;" :: "n"(N) : "memory")

__device__ __forceinline__ void ldsm4(uint32_t& r0, uint32_t& r1, uint32_t& r2, uint32_t& r3,
                                      uint32_t addr) {
    asm volatile("ldmatrix.sync.aligned.m8n8.x4.shared.b16 {%0,%1,%2,%3}, [%4];"
                 : "=r"(r0), "=r"(r1), "=r"(r2), "=r"(r3) : "r"(addr));
}
__device__ __forceinline__ void mma16816(float& d0, float& d1, float& d2, float& d3,
                                         uint32_t a0, uint32_t a1, uint32_t a2, uint32_t a3,
                                         uint32_t b0, uint32_t b1) {
    asm volatile("mma.sync.aligned.m16n8k16.row.col.f32.bf16.bf16.f32 "
                 "{%0,%1,%2,%3}, {%4,%5,%6,%7}, {%8,%9}, {%0,%1,%2,%3};"
                 : "+f"(d0), "+f"(d1), "+f"(d2), "+f"(d3)
                 : "r"(a0), "r"(a1), "r"(a2), "r"(a3), "r"(b0), "r"(b1));
}

// ---------------------------------------------------------------------------
// mask_pack: int32 mask [b][sq][sk] -> bit per element (1 = keep)
// ---------------------------------------------------------------------------
__global__ __launch_bounds__(256)
void mask_pack(const int* __restrict__ mask, uint32_t* __restrict__ bits)
{
    const size_t tid = (size_t)blockIdx.x * 256 + threadIdx.x;
    const int lane = threadIdx.x & 31;
    const int mv = mask[tid];
    const uint32_t w = __ballot_sync(0xffffffffu, mv != 0);
    if (lane == 0) bits[tid >> 5] = w;
}

// ---------------------------------------------------------------------------
// split: X fp32 [rows][1024] -> Y bf16 [rows][3072]
// SIDE 0 (A operand): (hi,hi,lo);  SIDE 1 (B): (hi,lo,hi)
// ---------------------------------------------------------------------------
template<int SIDE>
__global__ __launch_bounds__(256)
void split_kernel(const float* __restrict__ X, __nv_bfloat16* __restrict__ Y)
{
    const int idx = blockIdx.x * 256 + threadIdx.x;
    const int r   = idx >> 8;
    const int c4  = (idx & 255) * 4;
    const float4 x = *(const float4*)(X + (size_t)r * DM + c4);

    __nv_bfloat16 h0 = __float2bfloat16(x.x), h1 = __float2bfloat16(x.y);
    __nv_bfloat16 h2 = __float2bfloat16(x.z), h3 = __float2bfloat16(x.w);
    __nv_bfloat16 l0 = __float2bfloat16(x.x - __bfloat162float(h0));
    __nv_bfloat16 l1 = __float2bfloat16(x.y - __bfloat162float(h1));
    __nv_bfloat16 l2 = __float2bfloat16(x.z - __bfloat162float(h2));
    __nv_bfloat16 l3 = __float2bfloat16(x.w - __bfloat162float(h3));

    __nv_bfloat162 hA = __halves2bfloat162(h0,h1), hB = __halves2bfloat162(h2,h3);
    __nv_bfloat162 lA = __halves2bfloat162(l0,l1), lB = __halves2bfloat162(l2,l3);

    __nv_bfloat162* y0 = (__nv_bfloat162*)(Y + (size_t)r * GK + c4);
    __nv_bfloat162* y1 = (__nv_bfloat162*)(Y + (size_t)r * GK + 1024 + c4);
    __nv_bfloat162* y2 = (__nv_bfloat162*)(Y + (size_t)r * GK + 2048 + c4);
    y0[0] = hA; y0[1] = hB;
    if (SIDE == 0) { y1[0] = hA; y1[1] = hB; y2[0] = lA; y2[1] = lB; }
    else           { y1[0] = lA; y1[1] = lB; y2[0] = hA; y2[1] = hB; }
}

// ---------------------------------------------------------------------------
// HMMA GEMM.  MODE 0: out fp32 [m][1024] (+bias)
//             MODE 1: out = Q split bf16 [bh][s][192] (hi,hi,lo)
//             MODE 2: out = K split bf16 [bh][s][192] (hi,lo,hi)
// ---------------------------------------------------------------------------
#define ROWB   80
#define TILEB  (128*ROWB)
#define HS_A0  0
#define HS_B0  TILEB
#define HS_A1  (2*TILEB)
#define HS_B1  (3*TILEB)
#define HSMEM  (4*TILEB)

template<int MODE>
__device__ __forceinline__ void store_qk_split(__nv_bfloat16* Y, int m, int col, float2 w)
{
    const int b = m >> 11, s = m & (SEQ-1);
    const int h = col >> 6, d = col & 63;
    __nv_bfloat16* base = Y + ((size_t)(b*HEADS + h) * SEQ + s) * 192 + d;
    __nv_bfloat16 hx = __float2bfloat16(w.x), hy = __float2bfloat16(w.y);
    __nv_bfloat162 hi = __halves2bfloat162(hx, hy);
    __nv_bfloat162 lo = __floats2bfloat162_rn(w.x - __bfloat162float(hx),
                                              w.y - __bfloat162float(hy));
    *(__nv_bfloat162*)(base) = hi;
    if (MODE == 1) { *(__nv_bfloat162*)(base + 64) = hi; *(__nv_bfloat162*)(base + 128) = lo; }
    else           { *(__nv_bfloat162*)(base + 64) = lo; *(__nv_bfloat162*)(base + 128) = hi; }
}

template<int MODE>
__global__ __launch_bounds__(256, 2)
void hgemm(const __nv_bfloat16* __restrict__ A, const __nv_bfloat16* __restrict__ B,
           const float* __restrict__ bias, void* __restrict__ outp)
{
    extern __shared__ char sm[];
    const uint32_t sbase = smem_u32(sm);
    const int tid  = threadIdx.x;
    const int m0   = blockIdx.x * 128;
    const int n0   = blockIdx.y * 128;

    const int r0c = tid >> 2,  c0c = tid & 3;
    const int r1c = r0c + 64;
    const __nv_bfloat16* Ag0 = A + (size_t)(m0 + r0c) * GK + c0c * 8;
    const __nv_bfloat16* Ag1 = A + (size_t)(m0 + r1c) * GK + c0c * 8;
    const __nv_bfloat16* Bg0 = B + (size_t)(n0 + r0c) * GK + c0c * 8;
    const __nv_bfloat16* Bg1 = B + (size_t)(n0 + r1c) * GK + c0c * 8;
    const uint32_t sA_off0 = r0c * ROWB + c0c * 16;
    const uint32_t sA_off1 = r1c * ROWB + c0c * 16;

    const uint32_t abuf[2] = { sbase + HS_A0, sbase + HS_A1 };
    const uint32_t bbuf[2] = { sbase + HS_B0, sbase + HS_B1 };

    const int wid  = tid >> 5, lane = tid & 31;
    const int wm   = (wid >> 2) * 64;
    const int wn   = (wid & 3) * 32;

    const uint32_t aoff = (uint32_t)(wm + (lane & 15)) * ROWB + (lane >> 4) * 16;
    const uint32_t boff = (uint32_t)(wn + ((lane >> 4) & 1) * 8 + (lane & 7)) * ROWB
                        + ((lane >> 3) & 1) * 16;

    float acc[4][4][4] = {};

    #define LOAD_TILE(it, buf) do {                                            \
        const size_t kb = (size_t)(it) * 32;                                   \
        cpa16(abuf[buf] + sA_off0, Ag0 + kb);                                  \
        cpa16(abuf[buf] + sA_off1, Ag1 + kb);                                  \
        cpa16(bbuf[buf] + sA_off0, Bg0 + kb);                                  \
        cpa16(bbuf[buf] + sA_off1, Bg1 + kb);                                  \
        CPA_COMMIT();                                                          \
    } while (0)

    LOAD_TILE(0, 0);

    const int KITERS = GK / 32;
    for (int it = 0; it < KITERS; it++) {
        const int cur = it & 1;
        if (it + 1 < KITERS) { LOAD_TILE(it + 1, cur ^ 1); CPA_WAIT(1); }
        else                 { CPA_WAIT(0); }
        __syncthreads();

        #pragma unroll
        for (int kk = 0; kk < 2; kk++) {
            const uint32_t kb = kk * 32;
            uint32_t a[4][4], b[4][2];
            #pragma unroll
            for (int mt = 0; mt < 4; mt++)
                ldsm4(a[mt][0], a[mt][1], a[mt][2], a[mt][3],
                      abuf[cur] + aoff + (uint32_t)mt * (16*ROWB) + kb);
            #pragma unroll
            for (int np = 0; np < 2; np++) {
                uint32_t q0,q1,q2,q3;
                ldsm4(q0,q1,q2,q3, bbuf[cur] + boff + (uint32_t)np * (16*ROWB) + kb);
                b[np*2+0][0] = q0; b[np*2+0][1] = q1;
                b[np*2+1][0] = q2; b[np*2+1][1] = q3;
            }
            #pragma unroll
            for (int mt = 0; mt < 4; mt++)
                #pragma unroll
                for (int nt = 0; nt < 4; nt++)
                    mma16816(acc[mt][nt][0], acc[mt][nt][1], acc[mt][nt][2], acc[mt][nt][3],
                             a[mt][0], a[mt][1], a[mt][2], a[mt][3],
                             b[nt][0], b[nt][1]);
        }
        __syncthreads();
    }

    const int erow = lane >> 2;
    const int ecol = (lane & 3) * 2;
    #pragma unroll
    for (int nt = 0; nt < 4; nt++) {
        const int col = n0 + wn + nt * 8 + ecol;
        const float2 bv = *(const float2*)(bias + col);
        #pragma unroll
        for (int mt = 0; mt < 4; mt++) {
            const int m = m0 + wm + mt * 16 + erow;
            float2 w0, w1;
            w0.x = acc[mt][nt][0] + bv.x; w0.y = acc[mt][nt][1] + bv.y;
            w1.x = acc[mt][nt][2] + bv.x; w1.y = acc[mt][nt][3] + bv.y;
            if (MODE == 0) {
                float* out = (float*)outp;
                *(float2*)(out + (size_t)m * DM + col)       = w0;
                *(float2*)(out + (size_t)(m + 8) * DM + col) = w1;
            } else {
                __nv_bfloat16* out = (__nv_bfloat16*)outp;
                store_qk_split<MODE>(out, m,     col, w0);
                store_qk_split<MODE>(out, m + 8, col, w1);
            }
        }
    }
    #undef LOAD_TILE
}

// ---------------------------------------------------------------------------
// v_split: fp32 [m][1024] -> bf16 transposed [bh][seg][d=64][s=2048]
// ---------------------------------------------------------------------------
__global__ __launch_bounds__(256)
void v_split(const float* __restrict__ V, __nv_bfloat16* __restrict__ Y)
{
    __shared__ float sm[64][132];
    const int bh = blockIdx.y;
    const int b = bh >> 4, h = bh & 15;
    const int sblk = blockIdx.x * 128;
    const int t = threadIdx.x;

    {
        const int srow = t >> 1, half = (t & 1) * 32;
        const float* src = V + ((size_t)b * SEQ + sblk + srow) * DM + h * DKH + half;
        #pragma unroll
        for (int j = 0; j < 8; j++) {
            const float4 v = *(const float4*)(src + j*4);
            sm[half + j*4 + 0][srow] = v.x;
            sm[half + j*4 + 1][srow] = v.y;
            sm[half + j*4 + 2][srow] = v.z;
            sm[half + j*4 + 3][srow] = v.w;
        }
    }
    __syncthreads();
    {
        const int d = t >> 2, sc = (t & 3) * 32;
        __nv_bfloat162* dh = (__nv_bfloat162*)(Y + (((size_t)bh*2 + 0) * DKH + d) * SEQ + sblk + sc);
        __nv_bfloat162* dl = (__nv_bfloat162*)(Y + (((size_t)bh*2 + 1) * DKH + d) * SEQ + sblk + sc);
        #pragma unroll
        for (int j = 0; j < 16; j++) {
            const float a = sm[d][sc + j*2], c = sm[d][sc + j*2 + 1];
            __nv_bfloat16 ha = __float2bfloat16(a), hc = __float2bfloat16(c);
            __nv_bfloat16 la = __float2bfloat16(a - __bfloat162float(ha));
            __nv_bfloat16 lc = __float2bfloat16(c - __bfloat162float(hc));
            dh[j] = __halves2bfloat162(ha, hc);
            dl[j] = __halves2bfloat162(la, lc);
        }
    }
}

// ---------------------------------------------------------------------------
// HMMA flash attention (R6 config: 128 q-rows, 8 warps, double-buffered K/V)
// + exp2 softmax, prefetched bit-mask, half-split softmax->PV,
// epilogue writes split-bf16 ctx [m][3072] (A-side: hi,hi,lo) directly.
// smem: Qs [128][400B] | K0,K1 [128][400B] | V0,V1 [2][64][272B]
// ---------------------------------------------------------------------------
#define QROWB 400
#define VROWB 272
#define AS_Q  0
#define AS_K0 51200
#define AS_K1 102400
#define AS_V0 153600
#define AS_V1 188416
#define ASMEM 223232
#define LOG2E_8TH 0.1803368801111204f   // 0.125 * log2(e)

__global__ __launch_bounds__(256, 1)
void attn_mma(const __nv_bfloat16* __restrict__ Qs, const __nv_bfloat16* __restrict__ Ks,
              const __nv_bfloat16* __restrict__ Vt, const uint32_t* __restrict__ mbits,
              __nv_bfloat16* __restrict__ cb)
{
    extern __shared__ char sm[];
    const uint32_t sb = smem_u32(sm);
    const int tid  = threadIdx.x;
    const int lane = tid & 31;
    const int wm   = (tid >> 5) * 16;
    const int bh   = blockIdx.y;
    const int b    = bh >> 4, h = bh & 15;
    const int q0g  = blockIdx.x * 128;

    const __nv_bfloat16* qb = Qs + ((size_t)bh * SEQ + q0g) * 192;
    const __nv_bfloat16* kb = Ks + (size_t)bh * SEQ * 192;
    const __nv_bfloat16* vb = Vt + (size_t)bh * 2 * DKH * SEQ;

    const int lrow = tid >> 1, lhalf = tid & 1;

    // Q tile once
    {
        const uint32_t sq = sb + AS_Q + lrow * QROWB + lhalf * 192;
        const __nv_bfloat16* gq = qb + (size_t)lrow * 192 + lhalf * 96;
        #pragma unroll
        for (int j = 0; j < 12; j++) cpa16(sq + j*16, gq + j*8);
        CPA_COMMIT();
    }

    const uint32_t kbuf[2] = { sb + AS_K0, sb + AS_K1 };
    const uint32_t vbuf[2] = { sb + AS_V0, sb + AS_V1 };

    const uint32_t aoffQ = sb + AS_Q + (uint32_t)(wm + (lane & 15)) * QROWB + (lane >> 4) * 16;
    const uint32_t boffK = (uint32_t)(((lane >> 4) & 1) * 8 + (lane & 7)) * QROWB
                         + ((lane >> 3) & 1) * 16;
    const uint32_t boffV = (uint32_t)(((lane >> 4) & 1) * 8 + (lane & 7)) * VROWB
                         + ((lane >> 3) & 1) * 16;

    const int r0 = lane >> 2;
    const int cql = (lane & 3) * 2;

    const uint32_t* mrow0 = mbits + ((size_t)b * SEQ + (q0g + wm + r0)) * (SEQ/32);
    const uint32_t* mrow1 = mrow0 + 8 * (SEQ/32);

    #define STAGE_KV(it, buf) do {                                                     \
        const int kb0_ = (it) * 128;                                                   \
        const uint32_t sk = kbuf[buf] + lrow * QROWB + lhalf * 192;                    \
        const __nv_bfloat16* gk = kb + ((size_t)(kb0_ + lrow)) * 192 + lhalf * 96;     \
        _Pragma("unroll")                                                              \
        for (int j = 0; j < 12; j++) cpa16(sk + j*16, gk + j*8);                       \
        const int seg_ = tid >> 7, vrow_ = (tid & 127) >> 1;                           \
        const uint32_t sv = vbuf[buf] + seg_ * (64*VROWB) + vrow_ * VROWB + lhalf*128; \
        const __nv_bfloat16* gv = vb + ((size_t)seg_ * DKH + vrow_) * SEQ + kb0_ + lhalf*64; \
        _Pragma("unroll")                                                              \
        for (int j = 0; j < 8; j++) cpa16(sv + j*16, gv + j*8);                        \
        CPA_COMMIT();                                                                  \
    } while (0)

    STAGE_KV(0, 0);

    float o[8][4] = {};
    float m0 = -1e30f, m1 = -1e30f, l0 = 0.f, l1 = 0.f;

    for (int it = 0; it < SEQ/128; it++) {
        const int cur = it & 1;
        const int kb0 = it * 128;

        // prefetch mask words (independent LDG, overlaps staging wait)
        const uint4 mq0 = *(const uint4*)(mrow0 + (kb0 >> 5));
        const uint4 mq1 = *(const uint4*)(mrow1 + (kb0 >> 5));

        if (it + 1 < SEQ/128) { STAGE_KV(it + 1, cur ^ 1); CPA_WAIT(1); }
        else                  { CPA_WAIT(0); }
        __syncthreads();

        // ---- S = Q K^T ----
        float s[16][4] = {};
        #pragma unroll
        for (int kk = 0; kk < 12; kk++) {
            uint32_t a0,a1,a2,a3;
            ldsm4(a0,a1,a2,a3, aoffQ + kk*32);
            #pragma unroll
            for (int np = 0; np < 8; np++) {
                uint32_t q0,q1,q2,q3;
                ldsm4(q0,q1,q2,q3, kbuf[cur] + boffK + (uint32_t)np * (16*QROWB) + kk*32);
                mma16816(s[2*np][0], s[2*np][1], s[2*np][2], s[2*np][3], a0,a1,a2,a3, q0,q1);
                mma16816(s[2*np+1][0], s[2*np+1][1], s[2*np+1][2], s[2*np+1][3], a0,a1,a2,a3, q2,q3);
            }
        }

        // ---- mask + scale (log2 units) + row max ----
        const uint32_t w0[4] = { mq0.x, mq0.y, mq0.z, mq0.w };
        const uint32_t w1[4] = { mq1.x, mq1.y, mq1.z, mq1.w };
        float mx0 = -1e30f, mx1 = -1e30f;
        #pragma unroll
        for (int t = 0; t < 16; t++) {
            const int sh = (t & 3) * 8 + cql;
            const uint32_t a = w0[t >> 2] >> sh;
            const uint32_t c = w1[t >> 2] >> sh;
            s[t][0] = (a & 1u) ? s[t][0] * LOG2E_8TH : -1e9f;
            s[t][1] = (a & 2u) ? s[t][1] * LOG2E_8TH : -1e9f;
            s[t][2] = (c & 1u) ? s[t][2] * LOG2E_8TH : -1e9f;
            s[t][3] = (c & 2u) ? s[t][3] * LOG2E_8TH : -1e9f;
            mx0 = fmaxf(mx0, fmaxf(s[t][0], s[t][1]));
            mx1 = fmaxf(mx1, fmaxf(s[t][2], s[t][3]));
        }
        mx0 = fmaxf(mx0, __shfl_xor_sync(0xffffffffu, mx0, 1));
        mx0 = fmaxf(mx0, __shfl_xor_sync(0xffffffffu, mx0, 2));
        mx1 = fmaxf(mx1, __shfl_xor_sync(0xffffffffu, mx1, 1));
        mx1 = fmaxf(mx1, __shfl_xor_sync(0xffffffffu, mx1, 2));

        const float nm0 = fmaxf(m0, mx0), nm1 = fmaxf(m1, mx1);
        const float c0 = exp2f(m0 - nm0), c1 = exp2f(m1 - nm1);
        m0 = nm0; m1 = nm1;

        // rescale O
        #pragma unroll
        for (int nt = 0; nt < 8; nt++) {
            o[nt][0] *= c0; o[nt][1] *= c0;
            o[nt][2] *= c1; o[nt][3] *= c1;
        }

        // ---- half-split: exp2 + pack + PV per 64-key half ----
        float rs0 = 0.f, rs1 = 0.f;
        #pragma unroll
        for (int half = 0; half < 2; half++) {
            uint32_t php[8][2], plp[8][2];
            #pragma unroll
            for (int tt = 0; tt < 8; tt++) {
                const int t = half*8 + tt;
                float p0 = exp2f(s[t][0] - nm0);
                float p1 = exp2f(s[t][1] - nm0);
                float p2 = exp2f(s[t][2] - nm1);
                float p3 = exp2f(s[t][3] - nm1);
                rs0 += p0 + p1; rs1 += p2 + p3;
                __nv_bfloat16 h0 = __float2bfloat16(p0), h1 = __float2bfloat16(p1);
                __nv_bfloat16 h2 = __float2bfloat16(p2), h3 = __float2bfloat16(p3);
                __nv_bfloat162 ph0 = __halves2bfloat162(h0, h1);
                __nv_bfloat162 ph1 = __halves2bfloat162(h2, h3);
                php[tt][0] = *(uint32_t*)&ph0;
                php[tt][1] = *(uint32_t*)&ph1;
                __nv_bfloat162 pl0 = __floats2bfloat162_rn(p0 - __bfloat162float(h0),
                                                           p1 - __bfloat162float(h1));
                __nv_bfloat162 pl1 = __floats2bfloat162_rn(p2 - __bfloat162float(h2),
                                                           p3 - __bfloat162float(h3));
                plp[tt][0] = *(uint32_t*)&pl0;
                plp[tt][1] = *(uint32_t*)&pl1;
            }
            #pragma unroll
            for (int pass = 0; pass < 3; pass++) {
                const uint32_t vseg = (pass == 1) ? (uint32_t)(64*VROWB) : 0u;
                #pragma unroll
                for (int jj = 0; jj < 4; jj++) {
                    const int j = half*4 + jj;
                    uint32_t a0, a1, a2, a3;
                    if (pass == 2) { a0 = plp[2*jj][0]; a1 = plp[2*jj][1]; a2 = plp[2*jj+1][0]; a3 = plp[2*jj+1][1]; }
                    else           { a0 = php[2*jj][0]; a1 = php[2*jj][1]; a2 = php[2*jj+1][0]; a3 = php[2*jj+1][1]; }
                    #pragma unroll
                    for (int np = 0; np < 4; np++) {
                        uint32_t q0,q1,q2,q3;
                        ldsm4(q0,q1,q2,q3, vbuf[cur] + boffV + vseg + (uint32_t)np * (16*VROWB) + j*32);
                        mma16816(o[2*np][0], o[2*np][1], o[2*np][2], o[2*np][3], a0,a1,a2,a3, q0,q1);
                        mma16816(o[2*np+1][0], o[2*np+1][1], o[2*np+1][2], o[2*np+1][3], a0,a1,a2,a3, q2,q3);
                    }
                }
            }
        }
        l0 = l0 * c0;
        l1 = l1 * c1;
        rs0 += __shfl_xor_sync(0xffffffffu, rs0, 1);
        rs0 += __shfl_xor_sync(0xffffffffu, rs0, 2);
        rs1 += __shfl_xor_sync(0xffffffffu, rs1, 1);
        rs1 += __shfl_xor_sync(0xffffffffu, rs1, 2);
        l0 += rs0;
        l1 += rs1;

        __syncthreads();   // all reads of buffer `cur` done before restaging
    }

    // ---- normalize & write split-bf16 ctx (A-side: hi,hi,lo) ----
    const float i0 = 1.f / l0, i1 = 1.f / l1;
    const int row0 = q0g + wm + r0;
    __nv_bfloat16* c0p = cb + ((size_t)b * SEQ + row0) * GK + h * DKH;
    __nv_bfloat16* c1p = cb + ((size_t)b * SEQ + row0 + 8) * GK + h * DKH;
    #pragma unroll
    for (int nt = 0; nt < 8; nt++) {
        const int col = nt * 8 + cql;
        const float x0 = o[nt][0] * i0, y0 = o[nt][1] * i0;
        const float x1 = o[nt][2] * i1, y1 = o[nt][3] * i1;
        {
            __nv_bfloat16 hx = __float2bfloat16(x0), hy = __float2bfloat16(y0);
            __nv_bfloat162 hi = __halves2bfloat162(hx, hy);
            __nv_bfloat162 lo = __floats2bfloat162_rn(x0 - __bfloat162float(hx),
                                                      y0 - __bfloat162float(hy));
            *(__nv_bfloat162*)(c0p + col)        = hi;
            *(__nv_bfloat162*)(c0p + 1024 + col) = hi;
            *(__nv_bfloat162*)(c0p + 2048 + col) = lo;
        }
        {
            __nv_bfloat16 hx = __float2bfloat16(x1), hy = __float2bfloat16(y1);
            __nv_bfloat162 hi = __halves2bfloat162(hx, hy);
            __nv_bfloat162 lo = __floats2bfloat162_rn(x1 - __bfloat162float(hx),
                                                      y1 - __bfloat162float(hy));
            *(__nv_bfloat162*)(c1p + col)        = hi;
            *(__nv_bfloat162*)(c1p + 1024 + col) = hi;
            *(__nv_bfloat162*)(c1p + 2048 + col) = lo;
        }
    }
    #undef STAGE_KV
}

// ---------------------------------------------------------------------------
extern "C" void kernel_launch(void* const* d_in, const int* in_sizes, int n_in,
                              void* d_out, int out_size)
{
    (void)in_sizes; (void)n_in; (void)out_size;
    const float* hid  = (const float*)d_in[0];
    const int*   mask = (const int*)  d_in[1];
    const float* Wq   = (const float*)d_in[2];
    const float* bq   = (const float*)d_in[3];
    const float* Wk   = (const float*)d_in[4];
    const float* bk   = (const float*)d_in[5];
    const float* Wv   = (const float*)d_in[6];
    const float* bv   = (const float*)d_in[7];
    const float* Wo   = (const float*)d_in[8];
    const float* bo   = (const float*)d_in[9];
    float* out = (float*)d_out;

    uint4 *ab, *wb, *cb, *qs, *ks, *vt;
    float *vp;
    uint32_t* mbp;
    cudaGetSymbolAddress((void**)&ab, g_abig);
    cudaGetSymbolAddress((void**)&wb, g_wbig);
    cudaGetSymbolAddress((void**)&cb, g_cbig);
    cudaGetSymbolAddress((void**)&qs, g_qs);
    cudaGetSymbolAddress((void**)&ks, g_ks);
    cudaGetSymbolAddress((void**)&vt, g_vt);
    cudaGetSymbolAddress((void**)&vp, g_v);
    cudaGetSymbolAddress((void**)&mbp, g_mbits);

    const size_t WOFF = (size_t)DM * GK / 8;

    cudaFuncSetAttribute(attn_mma, cudaFuncAttributeMaxDynamicSharedMemorySize, ASMEM);

    mask_pack<<<(size_t)BATCH*SEQ*SEQ/256, 256>>>(mask, mbp);

    split_kernel<0><<<MTOT, 256>>>(hid, (__nv_bfloat16*)ab);
    split_kernel<1><<<DM, 256>>>(Wq, (__nv_bfloat16*)(wb + 0*WOFF));
    split_kernel<1><<<DM, 256>>>(Wk, (__nv_bfloat16*)(wb + 1*WOFF));
    split_kernel<1><<<DM, 256>>>(Wv, (__nv_bfloat16*)(wb + 2*WOFF));
    split_kernel<1><<<DM, 256>>>(Wo, (__nv_bfloat16*)(wb + 3*WOFF));

    const dim3 gg(MTOT/128, DM/128);
    hgemm<1><<<gg, 256, HSMEM>>>((const __nv_bfloat16*)ab, (const __nv_bfloat16*)(wb + 0*WOFF), bq, qs);
    hgemm<2><<<gg, 256, HSMEM>>>((const __nv_bfloat16*)ab, (const __nv_bfloat16*)(wb + 1*WOFF), bk, ks);
    hgemm<0><<<gg, 256, HSMEM>>>((const __nv_bfloat16*)ab, (const __nv_bfloat16*)(wb + 2*WOFF), bv, vp);

    v_split<<<dim3(SEQ/128, BATCH*HEADS), 256>>>(vp, (__nv_bfloat16*)vt);

    attn_mma<<<dim3(SEQ/128, BATCH*HEADS), 256, ASMEM>>>(
        (const __nv_bfloat16*)qs, (const __nv_bfloat16*)ks,
        (const __nv_bfloat16*)vt, mbp, (__nv_bfloat16*)cb);

    hgemm<0><<<gg, 256, HSMEM>>>((const __nv_bfloat16*)cb, (const __nv_bfloat16*)(wb + 3*WOFF), bo, out);
}

// round 11
// speedup vs baseline: 1.3675x; 1.2251x over previous
#include <cuda_runtime.h>
#include <cuda_bf16.h>
#include <cuda_fp16.h>
#include <stdint.h>
#include <math.h>

#define DM     1024
#define HEADS  16
#define DKH    64
#define BATCH  2
#define SEQ    2048
#define MTOT   (BATCH*SEQ)
#define GK     3072            // split-bf16 concatenated K (projections)

// ---------------- scratch (static device globals) --------------------------
__device__ uint4 g_abig[(size_t)MTOT * GK * 2 / 16];      // bf16 [4096][3072]
__device__ uint4 g_wbig[(size_t)4 * DM * GK * 2 / 16];    // 4 x bf16 [1024][3072]
__device__ uint4 g_cbig[(size_t)MTOT * GK * 2 / 16];      // bf16 [4096][3072] (split ctx)
__device__ float g_v[(size_t)MTOT * DM];                  // fp32 V [m][1024]
// attention operands (fp16, 2-term)
__device__ uint4 g_qs[(size_t)32 * SEQ * 128 * 2 / 16];   // fp16 [bh][s][128] (Qh,Ql)
__device__ uint4 g_ks[(size_t)32 * SEQ * 128 * 2 / 16];   // fp16 [bh][s][128] (Kh,Kh)
__device__ uint4 g_vt[(size_t)32 * DKH * SEQ * 2 / 16];   // fp16 [bh][d][s]
__device__ uint32_t g_mbits[(size_t)BATCH * SEQ * SEQ / 32]; // packed mask bits

// ---------------- small helpers --------------------------------------------
__device__ __forceinline__ uint32_t smem_u32(const void* p) {
    uint32_t a;
    asm("{ .reg .u64 t; cvta.to.shared.u64 t, %1; cvt.u32.u64 %0, t; }" : "=r"(a) : "l"(p));
    return a;
}
__device__ __forceinline__ void cpa16(uint32_t s, const void* g) {
    asm volatile("cp.async.cg.shared.global [%0], [%1], 16;" :: "r"(s), "l"(g));
}
#define CPA_COMMIT() asm volatile("cp.async.commit_group;" ::: "memory")
#define CPA_WAIT(N)  asm volatile("cp.async.wait_group %0;" :: "n"(N) : "memory")

__device__ __forceinline__ void ldsm4(uint32_t& r0, uint32_t& r1, uint32_t& r2, uint32_t& r3,
                                      uint32_t addr) {
    asm volatile("ldmatrix.sync.aligned.m8n8.x4.shared.b16 {%0,%1,%2,%3}, [%4];"
                 : "=r"(r0), "=r"(r1), "=r"(r2), "=r"(r3) : "r"(addr));
}
__device__ __forceinline__ void mma16816(float& d0, float& d1, float& d2, float& d3,
                                         uint32_t a0, uint32_t a1, uint32_t a2, uint32_t a3,
                                         uint32_t b0, uint32_t b1) {
    asm volatile("mma.sync.aligned.m16n8k16.row.col.f32.bf16.bf16.f32 "
                 "{%0,%1,%2,%3}, {%4,%5,%6,%7}, {%8,%9}, {%0,%1,%2,%3};"
                 : "+f"(d0), "+f"(d1), "+f"(d2), "+f"(d3)
                 : "r"(a0), "r"(a1), "r"(a2), "r"(a3), "r"(b0), "r"(b1));
}
__device__ __forceinline__ void mma16816h(float& d0, float& d1, float& d2, float& d3,
                                          uint32_t a0, uint32_t a1, uint32_t a2, uint32_t a3,
                                          uint32_t b0, uint32_t b1) {
    asm volatile("mma.sync.aligned.m16n8k16.row.col.f32.f16.f16.f32 "
                 "{%0,%1,%2,%3}, {%4,%5,%6,%7}, {%8,%9}, {%0,%1,%2,%3};"
                 : "+f"(d0), "+f"(d1), "+f"(d2), "+f"(d3)
                 : "r"(a0), "r"(a1), "r"(a2), "r"(a3), "r"(b0), "r"(b1));
}

// ---------------------------------------------------------------------------
// mask_pack: int32 mask [b][sq][sk] -> bit per element (1 = keep)
// ---------------------------------------------------------------------------
__global__ __launch_bounds__(256)
void mask_pack(const int* __restrict__ mask, uint32_t* __restrict__ bits)
{
    const size_t tid = (size_t)blockIdx.x * 256 + threadIdx.x;
    const int lane = threadIdx.x & 31;
    const int mv = mask[tid];
    const uint32_t w = __ballot_sync(0xffffffffu, mv != 0);
    if (lane == 0) bits[tid >> 5] = w;
}

// ---------------------------------------------------------------------------
// split: X fp32 [rows][1024] -> Y bf16 [rows][3072]
// SIDE 0 (A operand): (hi,hi,lo);  SIDE 1 (B): (hi,lo,hi)
// ---------------------------------------------------------------------------
template<int SIDE>
__global__ __launch_bounds__(256)
void split_kernel(const float* __restrict__ X, __nv_bfloat16* __restrict__ Y)
{
    const int idx = blockIdx.x * 256 + threadIdx.x;
    const int r   = idx >> 8;
    const int c4  = (idx & 255) * 4;
    const float4 x = *(const float4*)(X + (size_t)r * DM + c4);

    __nv_bfloat16 h0 = __float2bfloat16(x.x), h1 = __float2bfloat16(x.y);
    __nv_bfloat16 h2 = __float2bfloat16(x.z), h3 = __float2bfloat16(x.w);
    __nv_bfloat16 l0 = __float2bfloat16(x.x - __bfloat162float(h0));
    __nv_bfloat16 l1 = __float2bfloat16(x.y - __bfloat162float(h1));
    __nv_bfloat16 l2 = __float2bfloat16(x.z - __bfloat162float(h2));
    __nv_bfloat16 l3 = __float2bfloat16(x.w - __bfloat162float(h3));

    __nv_bfloat162 hA = __halves2bfloat162(h0,h1), hB = __halves2bfloat162(h2,h3);
    __nv_bfloat162 lA = __halves2bfloat162(l0,l1), lB = __halves2bfloat162(l2,l3);

    __nv_bfloat162* y0 = (__nv_bfloat162*)(Y + (size_t)r * GK + c4);
    __nv_bfloat162* y1 = (__nv_bfloat162*)(Y + (size_t)r * GK + 1024 + c4);
    __nv_bfloat162* y2 = (__nv_bfloat162*)(Y + (size_t)r * GK + 2048 + c4);
    y0[0] = hA; y0[1] = hB;
    if (SIDE == 0) { y1[0] = hA; y1[1] = hB; y2[0] = lA; y2[1] = lB; }
    else           { y1[0] = lA; y1[1] = lB; y2[0] = hA; y2[1] = hB; }
}

// ---------------------------------------------------------------------------
// HMMA GEMM.  MODE 0: out fp32 [m][1024] (+bias)
//             MODE 1: out = Q fp16 [bh][s][128] (Qh,Ql)
//             MODE 2: out = K fp16 [bh][s][128] (Kh,Kh)
// ---------------------------------------------------------------------------
#define ROWB   80
#define TILEB  (128*ROWB)
#define HS_A0  0
#define HS_B0  TILEB
#define HS_A1  (2*TILEB)
#define HS_B1  (3*TILEB)
#define HSMEM  (4*TILEB)

template<int MODE>
__device__ __forceinline__ void store_qk_fp16(__half* Y, int m, int col, float2 w)
{
    const int b = m >> 11, s = m & (SEQ-1);
    const int h = col >> 6, d = col & 63;
    __half* base = Y + ((size_t)(b*HEADS + h) * SEQ + s) * 128 + d;
    __half hx = __float2half_rn(w.x), hy = __float2half_rn(w.y);
    __half2 hi = __halves2half2(hx, hy);
    *(__half2*)(base) = hi;
    if (MODE == 1) {
        __half2 lo = __floats2half2_rn(w.x - __half2float(hx), w.y - __half2float(hy));
        *(__half2*)(base + 64) = lo;
    } else {
        *(__half2*)(base + 64) = hi;
    }
}

template<int MODE>
__global__ __launch_bounds__(256, 2)
void hgemm(const __nv_bfloat16* __restrict__ A, const __nv_bfloat16* __restrict__ B,
           const float* __restrict__ bias, void* __restrict__ outp)
{
    extern __shared__ char sm[];
    const uint32_t sbase = smem_u32(sm);
    const int tid  = threadIdx.x;
    const int m0   = blockIdx.x * 128;
    const int n0   = blockIdx.y * 128;

    const int r0c = tid >> 2,  c0c = tid & 3;
    const int r1c = r0c + 64;
    const __nv_bfloat16* Ag0 = A + (size_t)(m0 + r0c) * GK + c0c * 8;
    const __nv_bfloat16* Ag1 = A + (size_t)(m0 + r1c) * GK + c0c * 8;
    const __nv_bfloat16* Bg0 = B + (size_t)(n0 + r0c) * GK + c0c * 8;
    const __nv_bfloat16* Bg1 = B + (size_t)(n0 + r1c) * GK + c0c * 8;
    const uint32_t sA_off0 = r0c * ROWB + c0c * 16;
    const uint32_t sA_off1 = r1c * ROWB + c0c * 16;

    const uint32_t abuf[2] = { sbase + HS_A0, sbase + HS_A1 };
    const uint32_t bbuf[2] = { sbase + HS_B0, sbase + HS_B1 };

    const int wid  = tid >> 5, lane = tid & 31;
    const int wm   = (wid >> 2) * 64;
    const int wn   = (wid & 3) * 32;

    const uint32_t aoff = (uint32_t)(wm + (lane & 15)) * ROWB + (lane >> 4) * 16;
    const uint32_t boff = (uint32_t)(wn + ((lane >> 4) & 1) * 8 + (lane & 7)) * ROWB
                        + ((lane >> 3) & 1) * 16;

    float acc[4][4][4] = {};

    #define LOAD_TILE(it, buf) do {                                            \
        const size_t kb = (size_t)(it) * 32;                                   \
        cpa16(abuf[buf] + sA_off0, Ag0 + kb);                                  \
        cpa16(abuf[buf] + sA_off1, Ag1 + kb);                                  \
        cpa16(bbuf[buf] + sA_off0, Bg0 + kb);                                  \
        cpa16(bbuf[buf] + sA_off1, Bg1 + kb);                                  \
        CPA_COMMIT();                                                          \
    } while (0)

    LOAD_TILE(0, 0);

    const int KITERS = GK / 32;
    for (int it = 0; it < KITERS; it++) {
        const int cur = it & 1;
        if (it + 1 < KITERS) { LOAD_TILE(it + 1, cur ^ 1); CPA_WAIT(1); }
        else                 { CPA_WAIT(0); }
        __syncthreads();

        #pragma unroll
        for (int kk = 0; kk < 2; kk++) {
            const uint32_t kb = kk * 32;
            uint32_t a[4][4], b[4][2];
            #pragma unroll
            for (int mt = 0; mt < 4; mt++)
                ldsm4(a[mt][0], a[mt][1], a[mt][2], a[mt][3],
                      abuf[cur] + aoff + (uint32_t)mt * (16*ROWB) + kb);
            #pragma unroll
            for (int np = 0; np < 2; np++) {
                uint32_t q0,q1,q2,q3;
                ldsm4(q0,q1,q2,q3, bbuf[cur] + boff + (uint32_t)np * (16*ROWB) + kb);
                b[np*2+0][0] = q0; b[np*2+0][1] = q1;
                b[np*2+1][0] = q2; b[np*2+1][1] = q3;
            }
            #pragma unroll
            for (int mt = 0; mt < 4; mt++)
                #pragma unroll
                for (int nt = 0; nt < 4; nt++)
                    mma16816(acc[mt][nt][0], acc[mt][nt][1], acc[mt][nt][2], acc[mt][nt][3],
                             a[mt][0], a[mt][1], a[mt][2], a[mt][3],
                             b[nt][0], b[nt][1]);
        }
        __syncthreads();
    }

    const int erow = lane >> 2;
    const int ecol = (lane & 3) * 2;
    #pragma unroll
    for (int nt = 0; nt < 4; nt++) {
        const int col = n0 + wn + nt * 8 + ecol;
        const float2 bv = *(const float2*)(bias + col);
        #pragma unroll
        for (int mt = 0; mt < 4; mt++) {
            const int m = m0 + wm + mt * 16 + erow;
            float2 w0, w1;
            w0.x = acc[mt][nt][0] + bv.x; w0.y = acc[mt][nt][1] + bv.y;
            w1.x = acc[mt][nt][2] + bv.x; w1.y = acc[mt][nt][3] + bv.y;
            if (MODE == 0) {
                float* out = (float*)outp;
                *(float2*)(out + (size_t)m * DM + col)       = w0;
                *(float2*)(out + (size_t)(m + 8) * DM + col) = w1;
            } else {
                __half* out = (__half*)outp;
                store_qk_fp16<MODE>(out, m,     col, w0);
                store_qk_fp16<MODE>(out, m + 8, col, w1);
            }
        }
    }
    #undef LOAD_TILE
}

// ---------------------------------------------------------------------------
// v_half: fp32 [m][1024] -> fp16 transposed [bh][d=64][s=2048]
// ---------------------------------------------------------------------------
__global__ __launch_bounds__(256)
void v_half(const float* __restrict__ V, __half* __restrict__ Y)
{
    __shared__ float sm[64][132];
    const int bh = blockIdx.y;
    const int b = bh >> 4, h = bh & 15;
    const int sblk = blockIdx.x * 128;
    const int t = threadIdx.x;

    {
        const int srow = t >> 1, half = (t & 1) * 32;
        const float* src = V + ((size_t)b * SEQ + sblk + srow) * DM + h * DKH + half;
        #pragma unroll
        for (int j = 0; j < 8; j++) {
            const float4 v = *(const float4*)(src + j*4);
            sm[half + j*4 + 0][srow] = v.x;
            sm[half + j*4 + 1][srow] = v.y;
            sm[half + j*4 + 2][srow] = v.z;
            sm[half + j*4 + 3][srow] = v.w;
        }
    }
    __syncthreads();
    {
        const int d = t >> 2, sc = (t & 3) * 32;
        __half2* dh = (__half2*)(Y + ((size_t)bh * DKH + d) * SEQ + sblk + sc);
        #pragma unroll
        for (int j = 0; j < 16; j++)
            dh[j] = __floats2half2_rn(sm[d][sc + j*2], sm[d][sc + j*2 + 1]);
    }
}

// ---------------------------------------------------------------------------
// HMMA flash attention, fp16 2-term: Q=(Qh,Ql), K=(Kh,Kh) [128-dim],
// P split hi/lo fp16 (2 PV passes), V single fp16.
// 128 q-rows, 8 warps, double-buffered K/V, bit-mask, exp2 softmax,
// epilogue writes split-bf16 ctx [m][3072] (hi,hi,lo).
// smem: Q [128][272B] | K0,K1 [128][272B] | V0,V1 [64][272B] = 139264 B
// ---------------------------------------------------------------------------
#define QROWB 272
#define VROWB 272
#define AS_Q  0
#define AS_K0 34816
#define AS_K1 69632
#define AS_V0 104448
#define AS_V1 121856
#define ASMEM 139264
#define LOG2E_8TH 0.1803368801111204f   // 0.125 * log2(e)

__global__ __launch_bounds__(256, 1)
void attn_mma(const __half* __restrict__ Qs, const __half* __restrict__ Ks,
              const __half* __restrict__ Vt, const uint32_t* __restrict__ mbits,
              __nv_bfloat16* __restrict__ cb)
{
    extern __shared__ char sm[];
    const uint32_t sb = smem_u32(sm);
    const int tid  = threadIdx.x;
    const int lane = tid & 31;
    const int wm   = (tid >> 5) * 16;
    const int bh   = blockIdx.y;
    const int b    = bh >> 4, h = bh & 15;
    const int q0g  = blockIdx.x * 128;

    const __half* qb = Qs + ((size_t)bh * SEQ + q0g) * 128;
    const __half* kb = Ks + (size_t)bh * SEQ * 128;
    const __half* vb = Vt + (size_t)bh * DKH * SEQ;

    const int lrow = tid >> 1, lhalf = tid & 1;

    // Q tile once: 128 rows x 256B
    {
        const uint32_t sq = sb + AS_Q + lrow * QROWB + lhalf * 128;
        const __half* gq = qb + (size_t)lrow * 128 + lhalf * 64;
        #pragma unroll
        for (int j = 0; j < 8; j++) cpa16(sq + j*16, gq + j*8);
        CPA_COMMIT();
    }

    const uint32_t kbuf[2] = { sb + AS_K0, sb + AS_K1 };
    const uint32_t vbuf[2] = { sb + AS_V0, sb + AS_V1 };

    const uint32_t aoffQ = sb + AS_Q + (uint32_t)(wm + (lane & 15)) * QROWB + (lane >> 4) * 16;
    const uint32_t boffK = (uint32_t)(((lane >> 4) & 1) * 8 + (lane & 7)) * QROWB
                         + ((lane >> 3) & 1) * 16;
    const uint32_t boffV = (uint32_t)(((lane >> 4) & 1) * 8 + (lane & 7)) * VROWB
                         + ((lane >> 3) & 1) * 16;

    const int r0 = lane >> 2;
    const int cql = (lane & 3) * 2;

    const uint32_t* mrow0 = mbits + ((size_t)b * SEQ + (q0g + wm + r0)) * (SEQ/32);
    const uint32_t* mrow1 = mrow0 + 8 * (SEQ/32);

    #define STAGE_KV(it, buf) do {                                                     \
        const int kb0_ = (it) * 128;                                                   \
        const uint32_t sk = kbuf[buf] + lrow * QROWB + lhalf * 128;                    \
        const __half* gk = kb + ((size_t)(kb0_ + lrow)) * 128 + lhalf * 64;            \
        _Pragma("unroll")                                                              \
        for (int j = 0; j < 8; j++) cpa16(sk + j*16, gk + j*8);                        \
        const int vrow_ = tid >> 2, vcol_ = tid & 3;                                   \
        const uint32_t sv = vbuf[buf] + vrow_ * VROWB + vcol_ * 64;                    \
        const __half* gv = vb + (size_t)vrow_ * SEQ + kb0_ + vcol_ * 32;               \
        _Pragma("unroll")                                                              \
        for (int j = 0; j < 4; j++) cpa16(sv + j*16, gv + j*8);                        \
        CPA_COMMIT();                                                                  \
    } while (0)

    STAGE_KV(0, 0);

    float o[8][4] = {};
    float m0 = -1e30f, m1 = -1e30f, l0 = 0.f, l1 = 0.f;

    for (int it = 0; it < SEQ/128; it++) {
        const int cur = it & 1;
        const int kb0 = it * 128;

        // prefetch mask words (independent LDG, overlaps staging wait)
        const uint4 mq0 = *(const uint4*)(mrow0 + (kb0 >> 5));
        const uint4 mq1 = *(const uint4*)(mrow1 + (kb0 >> 5));

        if (it + 1 < SEQ/128) { STAGE_KV(it + 1, cur ^ 1); CPA_WAIT(1); }
        else                  { CPA_WAIT(0); }
        __syncthreads();

        // ---- S = Q K^T (fp16 2-term, 128-dim) ----
        float s[16][4] = {};
        #pragma unroll
        for (int kk = 0; kk < 8; kk++) {
            uint32_t a0,a1,a2,a3;
            ldsm4(a0,a1,a2,a3, aoffQ + kk*32);
            #pragma unroll
            for (int np = 0; np < 8; np++) {
                uint32_t q0,q1,q2,q3;
                ldsm4(q0,q1,q2,q3, kbuf[cur] + boffK + (uint32_t)np * (16*QROWB) + kk*32);
                mma16816h(s[2*np][0], s[2*np][1], s[2*np][2], s[2*np][3], a0,a1,a2,a3, q0,q1);
                mma16816h(s[2*np+1][0], s[2*np+1][1], s[2*np+1][2], s[2*np+1][3], a0,a1,a2,a3, q2,q3);
            }
        }

        // ---- mask + scale (log2 units) + row max ----
        const uint32_t w0[4] = { mq0.x, mq0.y, mq0.z, mq0.w };
        const uint32_t w1[4] = { mq1.x, mq1.y, mq1.z, mq1.w };
        float mx0 = -1e30f, mx1 = -1e30f;
        #pragma unroll
        for (int t = 0; t < 16; t++) {
            const int sh = (t & 3) * 8 + cql;
            const uint32_t a = w0[t >> 2] >> sh;
            const uint32_t c = w1[t >> 2] >> sh;
            s[t][0] = (a & 1u) ? s[t][0] * LOG2E_8TH : -1e9f;
            s[t][1] = (a & 2u) ? s[t][1] * LOG2E_8TH : -1e9f;
            s[t][2] = (c & 1u) ? s[t][2] * LOG2E_8TH : -1e9f;
            s[t][3] = (c & 2u) ? s[t][3] * LOG2E_8TH : -1e9f;
            mx0 = fmaxf(mx0, fmaxf(s[t][0], s[t][1]));
            mx1 = fmaxf(mx1, fmaxf(s[t][2], s[t][3]));
        }
        mx0 = fmaxf(mx0, __shfl_xor_sync(0xffffffffu, mx0, 1));
        mx0 = fmaxf(mx0, __shfl_xor_sync(0xffffffffu, mx0, 2));
        mx1 = fmaxf(mx1, __shfl_xor_sync(0xffffffffu, mx1, 1));
        mx1 = fmaxf(mx1, __shfl_xor_sync(0xffffffffu, mx1, 2));

        const float nm0 = fmaxf(m0, mx0), nm1 = fmaxf(m1, mx1);
        const float c0 = exp2f(m0 - nm0), c1 = exp2f(m1 - nm1);
        m0 = nm0; m1 = nm1;

        // rescale O
        #pragma unroll
        for (int nt = 0; nt < 8; nt++) {
            o[nt][0] *= c0; o[nt][1] *= c0;
            o[nt][2] *= c1; o[nt][3] *= c1;
        }

        // ---- half-split: exp2 + fp16 hi/lo pack + PV (2 passes) ----
        float rs0 = 0.f, rs1 = 0.f;
        #pragma unroll
        for (int half = 0; half < 2; half++) {
            uint32_t php[8][2], plp[8][2];
            #pragma unroll
            for (int tt = 0; tt < 8; tt++) {
                const int t = half*8 + tt;
                float p0 = exp2f(s[t][0] - nm0);
                float p1 = exp2f(s[t][1] - nm0);
                float p2 = exp2f(s[t][2] - nm1);
                float p3 = exp2f(s[t][3] - nm1);
                rs0 += p0 + p1; rs1 += p2 + p3;
                __half h0 = __float2half_rn(p0), h1 = __float2half_rn(p1);
                __half h2 = __float2half_rn(p2), h3 = __float2half_rn(p3);
                __half2 ph0 = __halves2half2(h0, h1);
                __half2 ph1 = __halves2half2(h2, h3);
                php[tt][0] = *(uint32_t*)&ph0;
                php[tt][1] = *(uint32_t*)&ph1;
                __half2 pl0 = __floats2half2_rn(p0 - __half2float(h0),
                                                p1 - __half2float(h1));
                __half2 pl1 = __floats2half2_rn(p2 - __half2float(h2),
                                                p3 - __half2float(h3));
                plp[tt][0] = *(uint32_t*)&pl0;
                plp[tt][1] = *(uint32_t*)&pl1;
            }
            #pragma unroll
            for (int pass = 0; pass < 2; pass++) {
                #pragma unroll
                for (int jj = 0; jj < 4; jj++) {
                    const int j = half*4 + jj;
                    uint32_t a0, a1, a2, a3;
                    if (pass == 1) { a0 = plp[2*jj][0]; a1 = plp[2*jj][1]; a2 = plp[2*jj+1][0]; a3 = plp[2*jj+1][1]; }
                    else           { a0 = php[2*jj][0]; a1 = php[2*jj][1]; a2 = php[2*jj+1][0]; a3 = php[2*jj+1][1]; }
                    #pragma unroll
                    for (int np = 0; np < 4; np++) {
                        uint32_t q0,q1,q2,q3;
                        ldsm4(q0,q1,q2,q3, vbuf[cur] + boffV + (uint32_t)np * (16*VROWB) + j*32);
                        mma16816h(o[2*np][0], o[2*np][1], o[2*np][2], o[2*np][3], a0,a1,a2,a3, q0,q1);
                        mma16816h(o[2*np+1][0], o[2*np+1][1], o[2*np+1][2], o[2*np+1][3], a0,a1,a2,a3, q2,q3);
                    }
                }
            }
        }
        l0 = l0 * c0;
        l1 = l1 * c1;
        rs0 += __shfl_xor_sync(0xffffffffu, rs0, 1);
        rs0 += __shfl_xor_sync(0xffffffffu, rs0, 2);
        rs1 += __shfl_xor_sync(0xffffffffu, rs1, 1);
        rs1 += __shfl_xor_sync(0xffffffffu, rs1, 2);
        l0 += rs0;
        l1 += rs1;

        __syncthreads();   // all reads of buffer `cur` done before restaging
    }

    // ---- normalize & write split-bf16 ctx (A-side: hi,hi,lo) ----
    const float i0 = 1.f / l0, i1 = 1.f / l1;
    const int row0 = q0g + wm + r0;
    __nv_bfloat16* c0p = cb + ((size_t)b * SEQ + row0) * GK + h * DKH;
    __nv_bfloat16* c1p = cb + ((size_t)b * SEQ + row0 + 8) * GK + h * DKH;
    #pragma unroll
    for (int nt = 0; nt < 8; nt++) {
        const int col = nt * 8 + cql;
        const float x0 = o[nt][0] * i0, y0 = o[nt][1] * i0;
        const float x1 = o[nt][2] * i1, y1 = o[nt][3] * i1;
        {
            __nv_bfloat16 hx = __float2bfloat16(x0), hy = __float2bfloat16(y0);
            __nv_bfloat162 hi = __halves2bfloat162(hx, hy);
            __nv_bfloat162 lo = __floats2bfloat162_rn(x0 - __bfloat162float(hx),
                                                      y0 - __bfloat162float(hy));
            *(__nv_bfloat162*)(c0p + col)        = hi;
            *(__nv_bfloat162*)(c0p + 1024 + col) = hi;
            *(__nv_bfloat162*)(c0p + 2048 + col) = lo;
        }
        {
            __nv_bfloat16 hx = __float2bfloat16(x1), hy = __float2bfloat16(y1);
            __nv_bfloat162 hi = __halves2bfloat162(hx, hy);
            __nv_bfloat162 lo = __floats2bfloat162_rn(x1 - __bfloat162float(hx),
                                                      y1 - __bfloat162float(hy));
            *(__nv_bfloat162*)(c1p + col)        = hi;
            *(__nv_bfloat162*)(c1p + 1024 + col) = hi;
            *(__nv_bfloat162*)(c1p + 2048 + col) = lo;
        }
    }
    #undef STAGE_KV
}

// ---------------------------------------------------------------------------
extern "C" void kernel_launch(void* const* d_in, const int* in_sizes, int n_in,
                              void* d_out, int out_size)
{
    (void)in_sizes; (void)n_in; (void)out_size;
    const float* hid  = (const float*)d_in[0];
    const int*   mask = (const int*)  d_in[1];
    const float* Wq   = (const float*)d_in[2];
    const float* bq   = (const float*)d_in[3];
    const float* Wk   = (const float*)d_in[4];
    const float* bk   = (const float*)d_in[5];
    const float* Wv   = (const float*)d_in[6];
    const float* bv   = (const float*)d_in[7];
    const float* Wo   = (const float*)d_in[8];
    const float* bo   = (const float*)d_in[9];
    float* out = (float*)d_out;

    uint4 *ab, *wb, *cb, *qs, *ks, *vt;
    float *vp;
    uint32_t* mbp;
    cudaGetSymbolAddress((void**)&ab, g_abig);
    cudaGetSymbolAddress((void**)&wb, g_wbig);
    cudaGetSymbolAddress((void**)&cb, g_cbig);
    cudaGetSymbolAddress((void**)&qs, g_qs);
    cudaGetSymbolAddress((void**)&ks, g_ks);
    cudaGetSymbolAddress((void**)&vt, g_vt);
    cudaGetSymbolAddress((void**)&vp, g_v);
    cudaGetSymbolAddress((void**)&mbp, g_mbits);

    const size_t WOFF = (size_t)DM * GK / 8;

    cudaFuncSetAttribute(attn_mma, cudaFuncAttributeMaxDynamicSharedMemorySize, ASMEM);

    mask_pack<<<(size_t)BATCH*SEQ*SEQ/256, 256>>>(mask, mbp);

    split_kernel<0><<<MTOT, 256>>>(hid, (__nv_bfloat16*)ab);
    split_kernel<1><<<DM, 256>>>(Wq, (__nv_bfloat16*)(wb + 0*WOFF));
    split_kernel<1><<<DM, 256>>>(Wk, (__nv_bfloat16*)(wb + 1*WOFF));
    split_kernel<1><<<DM, 256>>>(Wv, (__nv_bfloat16*)(wb + 2*WOFF));
    split_kernel<1><<<DM, 256>>>(Wo, (__nv_bfloat16*)(wb + 3*WOFF));

    const dim3 gg(MTOT/128, DM/128);
    hgemm<1><<<gg, 256, HSMEM>>>((const __nv_bfloat16*)ab, (const __nv_bfloat16*)(wb + 0*WOFF), bq, qs);
    hgemm<2><<<gg, 256, HSMEM>>>((const __nv_bfloat16*)ab, (const __nv_bfloat16*)(wb + 1*WOFF), bk, ks);
    hgemm<0><<<gg, 256, HSMEM>>>((const __nv_bfloat16*)ab, (const __nv_bfloat16*)(wb + 2*WOFF), bv, vp);

    v_half<<<dim3(SEQ/128, BATCH*HEADS), 256>>>(vp, (__half*)vt);

    attn_mma<<<dim3(SEQ/128, BATCH*HEADS), 256, ASMEM>>>(
        (const __half*)qs, (const __half*)ks,
        (const __half*)vt, mbp, (__nv_bfloat16*)cb);

    hgemm<0><<<gg, 256, HSMEM>>>((const __nv_bfloat16*)cb, (const __nv_bfloat16*)(wb + 3*WOFF), bo, out);
}

// round 13
// speedup vs baseline: 1.6261x; 1.1891x over previous
#include <cuda_runtime.h>
#include <cuda_bf16.h>
#include <cuda_fp16.h>
#include <stdint.h>
#include <math.h>

#define DM     1024
#define HEADS  16
#define DKH    64
#define BATCH  2
#define SEQ    2048
#define MTOT   (BATCH*SEQ)
#define GK     2048            // fp16 2-term concatenated K (projections)

// ---------------- scratch (static device globals) --------------------------
__device__ uint4 g_abig[(size_t)MTOT * GK * 2 / 16];      // fp16 [4096][2048] (Ah,Al)
__device__ uint4 g_wbig[(size_t)4 * DM * GK * 2 / 16];    // 4 x fp16 [1024][2048] (Wh,Wh)
__device__ uint4 g_cbig[(size_t)MTOT * GK * 2 / 16];      // fp16 [4096][2048] (Ch,Cl)
__device__ float g_v[(size_t)MTOT * DM];                  // fp32 V [m][1024]
// attention operands (fp16, 2-term)
__device__ uint4 g_qs[(size_t)32 * SEQ * 128 * 2 / 16];   // fp16 [bh][s][128] (Qh,Ql)
__device__ uint4 g_ks[(size_t)32 * SEQ * 128 * 2 / 16];   // fp16 [bh][s][128] (Kh,Kh)
__device__ uint4 g_vt[(size_t)32 * DKH * SEQ * 2 / 16];   // fp16 [bh][d][s]
__device__ uint32_t g_mbits[(size_t)BATCH * SEQ * SEQ / 32]; // packed mask bits

// ---------------- small helpers --------------------------------------------
__device__ __forceinline__ uint32_t smem_u32(const void* p) {
    uint32_t a;
    asm("{ .reg .u64 t; cvta.to.shared.u64 t, %1; cvt.u32.u64 %0, t; }" : "=r"(a) : "l"(p));
    return a;
}
__device__ __forceinline__ void cpa16(uint32_t s, const void* g) {
    asm volatile("cp.async.cg.shared.global [%0], [%1], 16;" :: "r"(s), "l"(g));
}
#define CPA_COMMIT() asm volatile("cp.async.commit_group;" ::: "memory")
#define CPA_WAIT(N)  asm volatile("cp.async.wait_group %0;" :: "n"(N) : "memory")

__device__ __forceinline__ void ldsm4(uint32_t& r0, uint32_t& r1, uint32_t& r2, uint32_t& r3,
                                      uint32_t addr) {
    asm volatile("ldmatrix.sync.aligned.m8n8.x4.shared.b16 {%0,%1,%2,%3}, [%4];"
                 : "=r"(r0), "=r"(r1), "=r"(r2), "=r"(r3) : "r"(addr));
}
__device__ __forceinline__ void mma16816h(float& d0, float& d1, float& d2, float& d3,
                                          uint32_t a0, uint32_t a1, uint32_t a2, uint32_t a3,
                                          uint32_t b0, uint32_t b1) {
    asm volatile("mma.sync.aligned.m16n8k16.row.col.f32.f16.f16.f32 "
                 "{%0,%1,%2,%3}, {%4,%5,%6,%7}, {%8,%9}, {%0,%1,%2,%3};"
                 : "+f"(d0), "+f"(d1), "+f"(d2), "+f"(d3)
                 : "r"(a0), "r"(a1), "r"(a2), "r"(a3), "r"(b0), "r"(b1));
}

// ---------------------------------------------------------------------------
// mask_pack: int32 mask [b][sq][sk] -> bit per element (1 = keep)
// ---------------------------------------------------------------------------
__global__ __launch_bounds__(256)
void mask_pack(const int* __restrict__ mask, uint32_t* __restrict__ bits)
{
    const size_t tid = (size_t)blockIdx.x * 256 + threadIdx.x;
    const int lane = threadIdx.x & 31;
    const int mv = mask[tid];
    const uint32_t w = __ballot_sync(0xffffffffu, mv != 0);
    if (lane == 0) bits[tid >> 5] = w;
}

// ---------------------------------------------------------------------------
// split: X fp32 [rows][1024] -> Y fp16 [rows][2048]
// SIDE 0 (A operand): (hi, lo);  SIDE 1 (B operand): (hi, hi)
// ---------------------------------------------------------------------------
template<int SIDE>
__global__ __launch_bounds__(256)
void split_kernel(const float* __restrict__ X, __half* __restrict__ Y)
{
    const int idx = blockIdx.x * 256 + threadIdx.x;
    const int r   = idx >> 8;
    const int c4  = (idx & 255) * 4;
    const float4 x = *(const float4*)(X + (size_t)r * DM + c4);

    __half h0 = __float2half_rn(x.x), h1 = __float2half_rn(x.y);
    __half h2 = __float2half_rn(x.z), h3 = __float2half_rn(x.w);

    __half2 hA = __halves2half2(h0,h1), hB = __halves2half2(h2,h3);

    __half2* y0 = (__half2*)(Y + (size_t)r * GK + c4);
    __half2* y1 = (__half2*)(Y + (size_t)r * GK + 1024 + c4);
    y0[0] = hA; y0[1] = hB;
    if (SIDE == 0) {
        __half2 lA = __floats2half2_rn(x.x - __half2float(h0), x.y - __half2float(h1));
        __half2 lB = __floats2half2_rn(x.z - __half2float(h2), x.w - __half2float(h3));
        y1[0] = lA; y1[1] = lB;
    } else {
        y1[0] = hA; y1[1] = hB;
    }
}

// ---------------------------------------------------------------------------
// HMMA GEMM (fp16 operands, fp32 accum, K = GK = 2048).
//   MODE 0: out fp32 [m][1024] (+bias)
//   MODE 1: out = Q fp16 [bh][s][128] (Qh,Ql)
//   MODE 2: out = K fp16 [bh][s][128] (Kh,Kh)
// ---------------------------------------------------------------------------
#define ROWB   80
#define TILEB  (128*ROWB)
#define HS_A0  0
#define HS_B0  TILEB
#define HS_A1  (2*TILEB)
#define HS_B1  (3*TILEB)
#define HSMEM  (4*TILEB)

template<int MODE>
__device__ __forceinline__ void store_qk_fp16(__half* Y, int m, int col, float2 w)
{
    const int b = m >> 11, s = m & (SEQ-1);
    const int h = col >> 6, d = col & 63;
    __half* base = Y + ((size_t)(b*HEADS + h) * SEQ + s) * 128 + d;
    __half hx = __float2half_rn(w.x), hy = __float2half_rn(w.y);
    __half2 hi = __halves2half2(hx, hy);
    *(__half2*)(base) = hi;
    if (MODE == 1) {
        __half2 lo = __floats2half2_rn(w.x - __half2float(hx), w.y - __half2float(hy));
        *(__half2*)(base + 64) = lo;
    } else {
        *(__half2*)(base + 64) = hi;
    }
}

template<int MODE>
__global__ __launch_bounds__(256, 2)
void hgemm(const __half* __restrict__ A, const __half* __restrict__ B,
           const float* __restrict__ bias, void* __restrict__ outp)
{
    extern __shared__ char sm[];
    const uint32_t sbase = smem_u32(sm);
    const int tid  = threadIdx.x;
    const int m0   = blockIdx.x * 128;
    const int n0   = blockIdx.y * 128;

    const int r0c = tid >> 2,  c0c = tid & 3;
    const int r1c = r0c + 64;
    const __half* Ag0 = A + (size_t)(m0 + r0c) * GK + c0c * 8;
    const __half* Ag1 = A + (size_t)(m0 + r1c) * GK + c0c * 8;
    const __half* Bg0 = B + (size_t)(n0 + r0c) * GK + c0c * 8;
    const __half* Bg1 = B + (size_t)(n0 + r1c) * GK + c0c * 8;
    const uint32_t sA_off0 = r0c * ROWB + c0c * 16;
    const uint32_t sA_off1 = r1c * ROWB + c0c * 16;

    const uint32_t abuf[2] = { sbase + HS_A0, sbase + HS_A1 };
    const uint32_t bbuf[2] = { sbase + HS_B0, sbase + HS_B1 };

    const int wid  = tid >> 5, lane = tid & 31;
    const int wm   = (wid >> 2) * 64;
    const int wn   = (wid & 3) * 32;

    const uint32_t aoff = (uint32_t)(wm + (lane & 15)) * ROWB + (lane >> 4) * 16;
    const uint32_t boff = (uint32_t)(wn + ((lane >> 4) & 1) * 8 + (lane & 7)) * ROWB
                        + ((lane >> 3) & 1) * 16;

    float acc[4][4][4] = {};

    #define LOAD_TILE(it, buf) do {                                            \
        const size_t kb = (size_t)(it) * 32;                                   \
        cpa16(abuf[buf] + sA_off0, Ag0 + kb);                                  \
        cpa16(abuf[buf] + sA_off1, Ag1 + kb);                                  \
        cpa16(bbuf[buf] + sA_off0, Bg0 + kb);                                  \
        cpa16(bbuf[buf] + sA_off1, Bg1 + kb);                                  \
        CPA_COMMIT();                                                          \
    } while (0)

    LOAD_TILE(0, 0);

    const int KITERS = GK / 32;   // 64
    for (int it = 0; it < KITERS; it++) {
        const int cur = it & 1;
        if (it + 1 < KITERS) { LOAD_TILE(it + 1, cur ^ 1); CPA_WAIT(1); }
        else                 { CPA_WAIT(0); }
        __syncthreads();

        #pragma unroll
        for (int kk = 0; kk < 2; kk++) {
            const uint32_t kb = kk * 32;
            uint32_t a[4][4], b[4][2];
            #pragma unroll
            for (int mt = 0; mt < 4; mt++)
                ldsm4(a[mt][0], a[mt][1], a[mt][2], a[mt][3],
                      abuf[cur] + aoff + (uint32_t)mt * (16*ROWB) + kb);
            #pragma unroll
            for (int np = 0; np < 2; np++) {
                uint32_t q0,q1,q2,q3;
                ldsm4(q0,q1,q2,q3, bbuf[cur] + boff + (uint32_t)np * (16*ROWB) + kb);
                b[np*2+0][0] = q0; b[np*2+0][1] = q1;
                b[np*2+1][0] = q2; b[np*2+1][1] = q3;
            }
            #pragma unroll
            for (int mt = 0; mt < 4; mt++)
                #pragma unroll
                for (int nt = 0; nt < 4; nt++)
                    mma16816h(acc[mt][nt][0], acc[mt][nt][1], acc[mt][nt][2], acc[mt][nt][3],
                              a[mt][0], a[mt][1], a[mt][2], a[mt][3],
                              b[nt][0], b[nt][1]);
        }
        __syncthreads();
    }

    const int erow = lane >> 2;
    const int ecol = (lane & 3) * 2;
    #pragma unroll
    for (int nt = 0; nt < 4; nt++) {
        const int col = n0 + wn + nt * 8 + ecol;
        const float2 bv = *(const float2*)(bias + col);
        #pragma unroll
        for (int mt = 0; mt < 4; mt++) {
            const int m = m0 + wm + mt * 16 + erow;
            float2 w0, w1;
            w0.x = acc[mt][nt][0] + bv.x; w0.y = acc[mt][nt][1] + bv.y;
            w1.x = acc[mt][nt][2] + bv.x; w1.y = acc[mt][nt][3] + bv.y;
            if (MODE == 0) {
                float* out = (float*)outp;
                *(float2*)(out + (size_t)m * DM + col)       = w0;
                *(float2*)(out + (size_t)(m + 8) * DM + col) = w1;
            } else {
                __half* out = (__half*)outp;
                store_qk_fp16<MODE>(out, m,     col, w0);
                store_qk_fp16<MODE>(out, m + 8, col, w1);
            }
        }
    }
    #undef LOAD_TILE
}

// ---------------------------------------------------------------------------
// v_half: fp32 [m][1024] -> fp16 transposed [bh][d=64][s=2048]
// ---------------------------------------------------------------------------
__global__ __launch_bounds__(256)
void v_half(const float* __restrict__ V, __half* __restrict__ Y)
{
    __shared__ float sm[64][132];
    const int bh = blockIdx.y;
    const int b = bh >> 4, h = bh & 15;
    const int sblk = blockIdx.x * 128;
    const int t = threadIdx.x;

    {
        const int srow = t >> 1, half = (t & 1) * 32;
        const float* src = V + ((size_t)b * SEQ + sblk + srow) * DM + h * DKH + half;
        #pragma unroll
        for (int j = 0; j < 8; j++) {
            const float4 v = *(const float4*)(src + j*4);
            sm[half + j*4 + 0][srow] = v.x;
            sm[half + j*4 + 1][srow] = v.y;
            sm[half + j*4 + 2][srow] = v.z;
            sm[half + j*4 + 3][srow] = v.w;
        }
    }
    __syncthreads();
    {
        const int d = t >> 2, sc = (t & 3) * 32;
        __half2* dh = (__half2*)(Y + ((size_t)bh * DKH + d) * SEQ + sblk + sc);
        #pragma unroll
        for (int j = 0; j < 16; j++)
            dh[j] = __floats2half2_rn(sm[d][sc + j*2], sm[d][sc + j*2 + 1]);
    }
}

// ---------------------------------------------------------------------------
// HMMA flash attention, fp16 2-term: Q=(Qh,Ql), K=(Kh,Kh) [128-dim],
// P split hi/lo fp16 (2 PV passes), V single fp16.
// 128 q-rows, 8 warps, double-buffered K/V, bit-mask, exp2 softmax,
// epilogue writes fp16 ctx [m][2048] (Ch,Cl).
// smem: Q [128][272B] | K0,K1 [128][272B] | V0,V1 [64][272B] = 139264 B
// ---------------------------------------------------------------------------
#define QROWB 272
#define VROWB 272
#define AS_Q  0
#define AS_K0 34816
#define AS_K1 69632
#define AS_V0 104448
#define AS_V1 121856
#define ASMEM 139264
#define LOG2E_8TH 0.1803368801111204f   // 0.125 * log2(e)

__global__ __launch_bounds__(256, 1)
void attn_mma(const __half* __restrict__ Qs, const __half* __restrict__ Ks,
              const __half* __restrict__ Vt, const uint32_t* __restrict__ mbits,
              __half* __restrict__ cb)
{
    extern __shared__ char sm[];
    const uint32_t sb = smem_u32(sm);
    const int tid  = threadIdx.x;
    const int lane = tid & 31;
    const int wm   = (tid >> 5) * 16;
    const int bh   = blockIdx.y;
    const int b    = bh >> 4, h = bh & 15;
    const int q0g  = blockIdx.x * 128;

    const __half* qb = Qs + ((size_t)bh * SEQ + q0g) * 128;
    const __half* kb = Ks + (size_t)bh * SEQ * 128;
    const __half* vb = Vt + (size_t)bh * DKH * SEQ;

    const int lrow = tid >> 1, lhalf = tid & 1;

    // Q tile once: 128 rows x 256B
    {
        const uint32_t sq = sb + AS_Q + lrow * QROWB + lhalf * 128;
        const __half* gq = qb + (size_t)lrow * 128 + lhalf * 64;
        #pragma unroll
        for (int j = 0; j < 8; j++) cpa16(sq + j*16, gq + j*8);
        CPA_COMMIT();
    }

    const uint32_t kbuf[2] = { sb + AS_K0, sb + AS_K1 };
    const uint32_t vbuf[2] = { sb + AS_V0, sb + AS_V1 };

    const uint32_t aoffQ = sb + AS_Q + (uint32_t)(wm + (lane & 15)) * QROWB + (lane >> 4) * 16;
    const uint32_t boffK = (uint32_t)(((lane >> 4) & 1) * 8 + (lane & 7)) * QROWB
                         + ((lane >> 3) & 1) * 16;
    const uint32_t boffV = (uint32_t)(((lane >> 4) & 1) * 8 + (lane & 7)) * VROWB
                         + ((lane >> 3) & 1) * 16;

    const int r0 = lane >> 2;
    const int cql = (lane & 3) * 2;

    const uint32_t* mrow0 = mbits + ((size_t)b * SEQ + (q0g + wm + r0)) * (SEQ/32);
    const uint32_t* mrow1 = mrow0 + 8 * (SEQ/32);

    #define STAGE_KV(it, buf) do {                                                     \
        const int kb0_ = (it) * 128;                                                   \
        const uint32_t sk = kbuf[buf] + lrow * QROWB + lhalf * 128;                    \
        const __half* gk = kb + ((size_t)(kb0_ + lrow)) * 128 + lhalf * 64;            \
        _Pragma("unroll")                                                              \
        for (int j = 0; j < 8; j++) cpa16(sk + j*16, gk + j*8);                        \
        const int vrow_ = tid >> 2, vcol_ = tid & 3;                                   \
        const uint32_t sv = vbuf[buf] + vrow_ * VROWB + vcol_ * 64;                    \
        const __half* gv = vb + (size_t)vrow_ * SEQ + kb0_ + vcol_ * 32;               \
        _Pragma("unroll")                                                              \
        for (int j = 0; j < 4; j++) cpa16(sv + j*16, gv + j*8);                        \
        CPA_COMMIT();                                                                  \
    } while (0)

    STAGE_KV(0, 0);

    float o[8][4] = {};
    float m0 = -1e30f, m1 = -1e30f, l0 = 0.f, l1 = 0.f;

    for (int it = 0; it < SEQ/128; it++) {
        const int cur = it & 1;
        const int kb0 = it * 128;

        // prefetch mask words (independent LDG, overlaps staging wait)
        const uint4 mq0 = *(const uint4*)(mrow0 + (kb0 >> 5));
        const uint4 mq1 = *(const uint4*)(mrow1 + (kb0 >> 5));

        if (it + 1 < SEQ/128) { STAGE_KV(it + 1, cur ^ 1); CPA_WAIT(1); }
        else                  { CPA_WAIT(0); }
        __syncthreads();

        // ---- S = Q K^T (fp16 2-term, 128-dim) ----
        float s[16][4] = {};
        #pragma unroll
        for (int kk = 0; kk < 8; kk++) {
            uint32_t a0,a1,a2,a3;
            ldsm4(a0,a1,a2,a3, aoffQ + kk*32);
            #pragma unroll
            for (int np = 0; np < 8; np++) {
                uint32_t q0,q1,q2,q3;
                ldsm4(q0,q1,q2,q3, kbuf[cur] + boffK + (uint32_t)np * (16*QROWB) + kk*32);
                mma16816h(s[2*np][0], s[2*np][1], s[2*np][2], s[2*np][3], a0,a1,a2,a3, q0,q1);
                mma16816h(s[2*np+1][0], s[2*np+1][1], s[2*np+1][2], s[2*np+1][3], a0,a1,a2,a3, q2,q3);
            }
        }

        // ---- mask + scale (log2 units) + row max ----
        const uint32_t w0[4] = { mq0.x, mq0.y, mq0.z, mq0.w };
        const uint32_t w1[4] = { mq1.x, mq1.y, mq1.z, mq1.w };
        float mx0 = -1e30f, mx1 = -1e30f;
        #pragma unroll
        for (int t = 0; t < 16; t++) {
            const int sh = (t & 3) * 8 + cql;
            const uint32_t a = w0[t >> 2] >> sh;
            const uint32_t c = w1[t >> 2] >> sh;
            s[t][0] = (a & 1u) ? s[t][0] * LOG2E_8TH : -1e9f;
            s[t][1] = (a & 2u) ? s[t][1] * LOG2E_8TH : -1e9f;
            s[t][2] = (c & 1u) ? s[t][2] * LOG2E_8TH : -1e9f;
            s[t][3] = (c & 2u) ? s[t][3] * LOG2E_8TH : -1e9f;
            mx0 = fmaxf(mx0, fmaxf(s[t][0], s[t][1]));
            mx1 = fmaxf(mx1, fmaxf(s[t][2], s[t][3]));
        }
        mx0 = fmaxf(mx0, __shfl_xor_sync(0xffffffffu, mx0, 1));
        mx0 = fmaxf(mx0, __shfl_xor_sync(0xffffffffu, mx0, 2));
        mx1 = fmaxf(mx1, __shfl_xor_sync(0xffffffffu, mx1, 1));
        mx1 = fmaxf(mx1, __shfl_xor_sync(0xffffffffu, mx1, 2));

        const float nm0 = fmaxf(m0, mx0), nm1 = fmaxf(m1, mx1);
        const float c0 = exp2f(m0 - nm0), c1 = exp2f(m1 - nm1);
        m0 = nm0; m1 = nm1;

        // rescale O
        #pragma unroll
        for (int nt = 0; nt < 8; nt++) {
            o[nt][0] *= c0; o[nt][1] *= c0;
            o[nt][2] *= c1; o[nt][3] *= c1;
        }

        // ---- half-split: exp2 + fp16 hi/lo pack + PV (2 passes) ----
        float rs0 = 0.f, rs1 = 0.f;
        #pragma unroll
        for (int half = 0; half < 2; half++) {
            uint32_t php[8][2], plp[8][2];
            #pragma unroll
            for (int tt = 0; tt < 8; tt++) {
                const int t = half*8 + tt;
                float p0 = exp2f(s[t][0] - nm0);
                float p1 = exp2f(s[t][1] - nm0);
                float p2 = exp2f(s[t][2] - nm1);
                float p3 = exp2f(s[t][3] - nm1);
                rs0 += p0 + p1; rs1 += p2 + p3;
                __half h0 = __float2half_rn(p0), h1 = __float2half_rn(p1);
                __half h2 = __float2half_rn(p2), h3 = __float2half_rn(p3);
                __half2 ph0 = __halves2half2(h0, h1);
                __half2 ph1 = __halves2half2(h2, h3);
                php[tt][0] = *(uint32_t*)&ph0;
                php[tt][1] = *(uint32_t*)&ph1;
                __half2 pl0 = __floats2half2_rn(p0 - __half2float(h0),
                                                p1 - __half2float(h1));
                __half2 pl1 = __floats2half2_rn(p2 - __half2float(h2),
                                                p3 - __half2float(h3));
                plp[tt][0] = *(uint32_t*)&pl0;
                plp[tt][1] = *(uint32_t*)&pl1;
            }
            #pragma unroll
            for (int pass = 0; pass < 2; pass++) {
                #pragma unroll
                for (int jj = 0; jj < 4; jj++) {
                    const int j = half*4 + jj;
                    uint32_t a0, a1, a2, a3;
                    if (pass == 1) { a0 = plp[2*jj][0]; a1 = plp[2*jj][1]; a2 = plp[2*jj+1][0]; a3 = plp[2*jj+1][1]; }
                    else           { a0 = php[2*jj][0]; a1 = php[2*jj][1]; a2 = php[2*jj+1][0]; a3 = php[2*jj+1][1]; }
                    #pragma unroll
                    for (int np = 0; np < 4; np++) {
                        uint32_t q0,q1,q2,q3;
                        ldsm4(q0,q1,q2,q3, vbuf[cur] + boffV + (uint32_t)np * (16*VROWB) + j*32);
                        mma16816h(o[2*np][0], o[2*np][1], o[2*np][2], o[2*np][3], a0,a1,a2,a3, q0,q1);
                        mma16816h(o[2*np+1][0], o[2*np+1][1], o[2*np+1][2], o[2*np+1][3], a0,a1,a2,a3, q2,q3);
                    }
                }
            }
        }
        l0 = l0 * c0;
        l1 = l1 * c1;
        rs0 += __shfl_xor_sync(0xffffffffu, rs0, 1);
        rs0 += __shfl_xor_sync(0xffffffffu, rs0, 2);
        rs1 += __shfl_xor_sync(0xffffffffu, rs1, 1);
        rs1 += __shfl_xor_sync(0xffffffffu, rs1, 2);
        l0 += rs0;
        l1 += rs1;

        __syncthreads();   // all reads of buffer `cur` done before restaging
    }

    // ---- normalize & write fp16 ctx (Ch at [0,1024), Cl at [1024,2048)) ----
    const float i0 = 1.f / l0, i1 = 1.f / l1;
    const int row0 = q0g + wm + r0;
    __half* c0p = cb + ((size_t)b * SEQ + row0) * GK + h * DKH;
    __half* c1p = cb + ((size_t)b * SEQ + row0 + 8) * GK + h * DKH;
    #pragma unroll
    for (int nt = 0; nt < 8; nt++) {
        const int col = nt * 8 + cql;
        const float x0 = o[nt][0] * i0, y0 = o[nt][1] * i0;
        const float x1 = o[nt][2] * i1, y1 = o[nt][3] * i1;
        {
            __half hx = __float2half_rn(x0), hy = __float2half_rn(y0);
            *(__half2*)(c0p + col)        = __halves2half2(hx, hy);
            *(__half2*)(c0p + 1024 + col) = __floats2half2_rn(x0 - __half2float(hx),
                                                              y0 - __half2float(hy));
        }
        {
            __half hx = __float2half_rn(x1), hy = __float2half_rn(y1);
            *(__half2*)(c1p + col)        = __halves2half2(hx, hy);
            *(__half2*)(c1p + 1024 + col) = __floats2half2_rn(x1 - __half2float(hx),
                                                              y1 - __half2float(hy));
        }
    }
    #undef STAGE_KV
}

// ---------------------------------------------------------------------------
extern "C" void kernel_launch(void* const* d_in, const int* in_sizes, int n_in,
                              void* d_out, int out_size)
{
    (void)in_sizes; (void)n_in; (void)out_size;
    const float* hid  = (const float*)d_in[0];
    const int*   mask = (const int*)  d_in[1];
    const float* Wq   = (const float*)d_in[2];
    const float* bq   = (const float*)d_in[3];
    const float* Wk   = (const float*)d_in[4];
    const float* bk   = (const float*)d_in[5];
    const float* Wv   = (const float*)d_in[6];
    const float* bv   = (const float*)d_in[7];
    const float* Wo   = (const float*)d_in[8];
    const float* bo   = (const float*)d_in[9];
    float* out = (float*)d_out;

    uint4 *ab, *wb, *cb, *qs, *ks, *vt;
    float *vp;
    uint32_t* mbp;
    cudaGetSymbolAddress((void**)&ab, g_abig);
    cudaGetSymbolAddress((void**)&wb, g_wbig);
    cudaGetSymbolAddress((void**)&cb, g_cbig);
    cudaGetSymbolAddress((void**)&qs, g_qs);
    cudaGetSymbolAddress((void**)&ks, g_ks);
    cudaGetSymbolAddress((void**)&vt, g_vt);
    cudaGetSymbolAddress((void**)&vp, g_v);
    cudaGetSymbolAddress((void**)&mbp, g_mbits);

    const size_t WOFF = (size_t)DM * GK / 8;   // uint4 per fp16 weight matrix

    cudaFuncSetAttribute(attn_mma, cudaFuncAttributeMaxDynamicSharedMemorySize, ASMEM);

    mask_pack<<<(size_t)BATCH*SEQ*SEQ/256, 256>>>(mask, mbp);

    split_kernel<0><<<MTOT, 256>>>(hid, (__half*)ab);
    split_kernel<1><<<DM, 256>>>(Wq, (__half*)(wb + 0*WOFF));
    split_kernel<1><<<DM, 256>>>(Wk, (__half*)(wb + 1*WOFF));
    split_kernel<1><<<DM, 256>>>(Wv, (__half*)(wb + 2*WOFF));
    split_kernel<1><<<DM, 256>>>(Wo, (__half*)(wb + 3*WOFF));

    const dim3 gg(MTOT/128, DM/128);
    hgemm<1><<<gg, 256, HSMEM>>>((const __half*)ab, (const __half*)(wb + 0*WOFF), bq, qs);
    hgemm<2><<<gg, 256, HSMEM>>>((const __half*)ab, (const __half*)(wb + 1*WOFF), bk, ks);
    hgemm<0><<<gg, 256, HSMEM>>>((const __half*)ab, (const __half*)(wb + 2*WOFF), bv, vp);

    v_half<<<dim3(SEQ/128, BATCH*HEADS), 256>>>(vp, (__half*)vt);

    attn_mma<<<dim3(SEQ/128, BATCH*HEADS), 256, ASMEM>>>(
        (const __half*)qs, (const __half*)ks,
        (const __half*)vt, mbp, (__half*)cb);

    hgemm<0><<<gg, 256, HSMEM>>>((const __half*)cb, (const __half*)(wb + 3*WOFF), bo, out);
}

// round 14
// speedup vs baseline: 1.7433x; 1.0721x over previous
#include <cuda_runtime.h>
#include <cuda_bf16.h>
#include <cuda_fp16.h>
#include <stdint.h>
#include <math.h>

#define DM     1024
#define HEADS  16
#define DKH    64
#define BATCH  2
#define SEQ    2048
#define MTOT   (BATCH*SEQ)
#define GK     2048            // fp16 2-term concatenated K (projections)

// ---------------- scratch (static device globals) --------------------------
__device__ uint4 g_abig[(size_t)MTOT * GK * 2 / 16];      // fp16 [4096][2048] (Ah,Al)
__device__ uint4 g_wbig[(size_t)4 * DM * GK * 2 / 16];    // 4 x fp16 [1024][2048] (Wh,Wh)
__device__ uint4 g_cbig[(size_t)MTOT * GK * 2 / 16];      // fp16 [4096][2048] (Ch,Cl)
__device__ float g_v[(size_t)MTOT * DM];                  // fp32 V [m][1024]
// attention operands (fp16, 2-term)
__device__ uint4 g_qs[(size_t)32 * SEQ * 128 * 2 / 16];   // fp16 [bh][s][128] (Qh,Ql)
__device__ uint4 g_ks[(size_t)32 * SEQ * 128 * 2 / 16];   // fp16 [bh][s][128] (Kh,Kh)
__device__ uint4 g_vt[(size_t)32 * DKH * SEQ * 2 / 16];   // fp16 [bh][d][s]
__device__ uint32_t g_mbits[(size_t)BATCH * SEQ * SEQ / 32]; // packed mask bits

// ---------------- small helpers --------------------------------------------
__device__ __forceinline__ uint32_t smem_u32(const void* p) {
    uint32_t a;
    asm("{ .reg .u64 t; cvta.to.shared.u64 t, %1; cvt.u32.u64 %0, t; }" : "=r"(a) : "l"(p));
    return a;
}
__device__ __forceinline__ void cpa16(uint32_t s, const void* g) {
    asm volatile("cp.async.cg.shared.global [%0], [%1], 16;" :: "r"(s), "l"(g));
}
#define CPA_COMMIT() asm volatile("cp.async.commit_group;" ::: "memory")
#define CPA_WAIT(N)  asm volatile("cp.async.wait_group %0;" :: "n"(N) : "memory")

__device__ __forceinline__ void ldsm4(uint32_t& r0, uint32_t& r1, uint32_t& r2, uint32_t& r3,
                                      uint32_t addr) {
    asm volatile("ldmatrix.sync.aligned.m8n8.x4.shared.b16 {%0,%1,%2,%3}, [%4];"
                 : "=r"(r0), "=r"(r1), "=r"(r2), "=r"(r3) : "r"(addr));
}
__device__ __forceinline__ void mma16816h(float& d0, float& d1, float& d2, float& d3,
                                          uint32_t a0, uint32_t a1, uint32_t a2, uint32_t a3,
                                          uint32_t b0, uint32_t b1) {
    asm volatile("mma.sync.aligned.m16n8k16.row.col.f32.f16.f16.f32 "
                 "{%0,%1,%2,%3}, {%4,%5,%6,%7}, {%8,%9}, {%0,%1,%2,%3};"
                 : "+f"(d0), "+f"(d1), "+f"(d2), "+f"(d3)
                 : "r"(a0), "r"(a1), "r"(a2), "r"(a3), "r"(b0), "r"(b1));
}

// ---------------------------------------------------------------------------
// mask_pack: int32 mask [b][sq][sk] -> bit per element (1 = keep)
// ---------------------------------------------------------------------------
__global__ __launch_bounds__(256)
void mask_pack(const int* __restrict__ mask, uint32_t* __restrict__ bits)
{
    const size_t tid = (size_t)blockIdx.x * 256 + threadIdx.x;
    const int lane = threadIdx.x & 31;
    const int mv = mask[tid];
    const uint32_t w = __ballot_sync(0xffffffffu, mv != 0);
    if (lane == 0) bits[tid >> 5] = w;
}

// ---------------------------------------------------------------------------
// split: X fp32 [rows][1024] -> Y fp16 [rows][2048]
// SIDE 0 (A operand): (hi, lo);  SIDE 1 (B operand): (hi, hi)
// ---------------------------------------------------------------------------
template<int SIDE>
__global__ __launch_bounds__(256)
void split_kernel(const float* __restrict__ X, __half* __restrict__ Y)
{
    const int idx = blockIdx.x * 256 + threadIdx.x;
    const int r   = idx >> 8;
    const int c4  = (idx & 255) * 4;
    const float4 x = *(const float4*)(X + (size_t)r * DM + c4);

    __half h0 = __float2half_rn(x.x), h1 = __float2half_rn(x.y);
    __half h2 = __float2half_rn(x.z), h3 = __float2half_rn(x.w);

    __half2 hA = __halves2half2(h0,h1), hB = __halves2half2(h2,h3);

    __half2* y0 = (__half2*)(Y + (size_t)r * GK + c4);
    __half2* y1 = (__half2*)(Y + (size_t)r * GK + 1024 + c4);
    y0[0] = hA; y0[1] = hB;
    if (SIDE == 0) {
        __half2 lA = __floats2half2_rn(x.x - __half2float(h0), x.y - __half2float(h1));
        __half2 lB = __floats2half2_rn(x.z - __half2float(h2), x.w - __half2float(h3));
        y1[0] = lA; y1[1] = lB;
    } else {
        y1[0] = hA; y1[1] = hB;
    }
}

// ---------------------------------------------------------------------------
// HMMA GEMM (fp16 operands, fp32 accum, K = GK = 2048).
//   MODE 0: out fp32 [m][1024] (+bias)
//   MODE 1: out = Q fp16 [bh][s][128] (Qh,Ql)
//   MODE 2: out = K fp16 [bh][s][128] (Kh,Kh)
// ---------------------------------------------------------------------------
#define ROWB   80
#define TILEB  (128*ROWB)
#define HS_A0  0
#define HS_B0  TILEB
#define HS_A1  (2*TILEB)
#define HS_B1  (3*TILEB)
#define HSMEM  (4*TILEB)

template<int MODE>
__device__ __forceinline__ void store_qk_fp16(__half* Y, int m, int col, float2 w)
{
    const int b = m >> 11, s = m & (SEQ-1);
    const int h = col >> 6, d = col & 63;
    __half* base = Y + ((size_t)(b*HEADS + h) * SEQ + s) * 128 + d;
    __half hx = __float2half_rn(w.x), hy = __float2half_rn(w.y);
    __half2 hi = __halves2half2(hx, hy);
    *(__half2*)(base) = hi;
    if (MODE == 1) {
        __half2 lo = __floats2half2_rn(w.x - __half2float(hx), w.y - __half2float(hy));
        *(__half2*)(base + 64) = lo;
    } else {
        *(__half2*)(base + 64) = hi;
    }
}

template<int MODE>
__global__ __launch_bounds__(256, 2)
void hgemm(const __half* __restrict__ A, const __half* __restrict__ B,
           const float* __restrict__ bias, void* __restrict__ outp)
{
    extern __shared__ char sm[];
    const uint32_t sbase = smem_u32(sm);
    const int tid  = threadIdx.x;
    const int m0   = blockIdx.x * 128;
    const int n0   = blockIdx.y * 128;

    const int r0c = tid >> 2,  c0c = tid & 3;
    const int r1c = r0c + 64;
    const __half* Ag0 = A + (size_t)(m0 + r0c) * GK + c0c * 8;
    const __half* Ag1 = A + (size_t)(m0 + r1c) * GK + c0c * 8;
    const __half* Bg0 = B + (size_t)(n0 + r0c) * GK + c0c * 8;
    const __half* Bg1 = B + (size_t)(n0 + r1c) * GK + c0c * 8;
    const uint32_t sA_off0 = r0c * ROWB + c0c * 16;
    const uint32_t sA_off1 = r1c * ROWB + c0c * 16;

    const uint32_t abuf[2] = { sbase + HS_A0, sbase + HS_A1 };
    const uint32_t bbuf[2] = { sbase + HS_B0, sbase + HS_B1 };

    const int wid  = tid >> 5, lane = tid & 31;
    const int wm   = (wid >> 2) * 64;
    const int wn   = (wid & 3) * 32;

    const uint32_t aoff = (uint32_t)(wm + (lane & 15)) * ROWB + (lane >> 4) * 16;
    const uint32_t boff = (uint32_t)(wn + ((lane >> 4) & 1) * 8 + (lane & 7)) * ROWB
                        + ((lane >> 3) & 1) * 16;

    float acc[4][4][4] = {};

    #define LOAD_TILE(it, buf) do {                                            \
        const size_t kb = (size_t)(it) * 32;                                   \
        cpa16(abuf[buf] + sA_off0, Ag0 + kb);                                  \
        cpa16(abuf[buf] + sA_off1, Ag1 + kb);                                  \
        cpa16(bbuf[buf] + sA_off0, Bg0 + kb);                                  \
        cpa16(bbuf[buf] + sA_off1, Bg1 + kb);                                  \
        CPA_COMMIT();                                                          \
    } while (0)

    LOAD_TILE(0, 0);

    const int KITERS = GK / 32;   // 64
    for (int it = 0; it < KITERS; it++) {
        const int cur = it & 1;
        if (it + 1 < KITERS) { LOAD_TILE(it + 1, cur ^ 1); CPA_WAIT(1); }
        else                 { CPA_WAIT(0); }
        __syncthreads();

        #pragma unroll
        for (int kk = 0; kk < 2; kk++) {
            const uint32_t kb = kk * 32;
            uint32_t a[4][4], b[4][2];
            #pragma unroll
            for (int mt = 0; mt < 4; mt++)
                ldsm4(a[mt][0], a[mt][1], a[mt][2], a[mt][3],
                      abuf[cur] + aoff + (uint32_t)mt * (16*ROWB) + kb);
            #pragma unroll
            for (int np = 0; np < 2; np++) {
                uint32_t q0,q1,q2,q3;
                ldsm4(q0,q1,q2,q3, bbuf[cur] + boff + (uint32_t)np * (16*ROWB) + kb);
                b[np*2+0][0] = q0; b[np*2+0][1] = q1;
                b[np*2+1][0] = q2; b[np*2+1][1] = q3;
            }
            #pragma unroll
            for (int mt = 0; mt < 4; mt++)
                #pragma unroll
                for (int nt = 0; nt < 4; nt++)
                    mma16816h(acc[mt][nt][0], acc[mt][nt][1], acc[mt][nt][2], acc[mt][nt][3],
                              a[mt][0], a[mt][1], a[mt][2], a[mt][3],
                              b[nt][0], b[nt][1]);
        }
        __syncthreads();
    }

    const int erow = lane >> 2;
    const int ecol = (lane & 3) * 2;
    #pragma unroll
    for (int nt = 0; nt < 4; nt++) {
        const int col = n0 + wn + nt * 8 + ecol;
        const float2 bv = *(const float2*)(bias + col);
        #pragma unroll
        for (int mt = 0; mt < 4; mt++) {
            const int m = m0 + wm + mt * 16 + erow;
            float2 w0, w1;
            w0.x = acc[mt][nt][0] + bv.x; w0.y = acc[mt][nt][1] + bv.y;
            w1.x = acc[mt][nt][2] + bv.x; w1.y = acc[mt][nt][3] + bv.y;
            if (MODE == 0) {
                float* out = (float*)outp;
                *(float2*)(out + (size_t)m * DM + col)       = w0;
                *(float2*)(out + (size_t)(m + 8) * DM + col) = w1;
            } else {
                __half* out = (__half*)outp;
                store_qk_fp16<MODE>(out, m,     col, w0);
                store_qk_fp16<MODE>(out, m + 8, col, w1);
            }
        }
    }
    #undef LOAD_TILE
}

// ---------------------------------------------------------------------------
// v_half: fp32 [m][1024] -> fp16 transposed [bh][d=64][s=2048]
// ---------------------------------------------------------------------------
__global__ __launch_bounds__(256)
void v_half(const float* __restrict__ V, __half* __restrict__ Y)
{
    __shared__ float sm[64][132];
    const int bh = blockIdx.y;
    const int b = bh >> 4, h = bh & 15;
    const int sblk = blockIdx.x * 128;
    const int t = threadIdx.x;

    {
        const int srow = t >> 1, half = (t & 1) * 32;
        const float* src = V + ((size_t)b * SEQ + sblk + srow) * DM + h * DKH + half;
        #pragma unroll
        for (int j = 0; j < 8; j++) {
            const float4 v = *(const float4*)(src + j*4);
            sm[half + j*4 + 0][srow] = v.x;
            sm[half + j*4 + 1][srow] = v.y;
            sm[half + j*4 + 2][srow] = v.z;
            sm[half + j*4 + 3][srow] = v.w;
        }
    }
    __syncthreads();
    {
        const int d = t >> 2, sc = (t & 3) * 32;
        __half2* dh = (__half2*)(Y + ((size_t)bh * DKH + d) * SEQ + sblk + sc);
        #pragma unroll
        for (int j = 0; j < 16; j++)
            dh[j] = __floats2half2_rn(sm[d][sc + j*2], sm[d][sc + j*2 + 1]);
    }
}

// ---------------------------------------------------------------------------
// HMMA flash attention, fp16 2-term, 64-key blocks, 2 CTAs/SM.
// 128 q-rows, 8 warps, double-buffered K/V, bit-mask, exp2 softmax,
// epilogue writes fp16 ctx [m][2048] (Ch,Cl).
// smem: Q [128][272B] | K0,K1 [64][272B] | V0,V1 [64][144B] = 88064 B
// ---------------------------------------------------------------------------
#define QROWB 272
#define KROWB 272
#define VROWB 144
#define AS_Q  0
#define AS_K0 34816
#define AS_K1 52224
#define AS_V0 69632
#define AS_V1 78848
#define ASMEM 88064
#define LOG2E_8TH 0.1803368801111204f   // 0.125 * log2(e)

__global__ __launch_bounds__(256, 2)
void attn_mma(const __half* __restrict__ Qs, const __half* __restrict__ Ks,
              const __half* __restrict__ Vt, const uint32_t* __restrict__ mbits,
              __half* __restrict__ cb)
{
    extern __shared__ char sm[];
    const uint32_t sb = smem_u32(sm);
    const int tid  = threadIdx.x;
    const int lane = tid & 31;
    const int wm   = (tid >> 5) * 16;
    const int bh   = blockIdx.y;
    const int b    = bh >> 4, h = bh & 15;
    const int q0g  = blockIdx.x * 128;

    const __half* qb = Qs + ((size_t)bh * SEQ + q0g) * 128;
    const __half* kb = Ks + (size_t)bh * SEQ * 128;
    const __half* vb = Vt + (size_t)bh * DKH * SEQ;

    // Q tile once: 128 rows x 256B
    {
        const int lrow = tid >> 1, lhalf = tid & 1;
        const uint32_t sq = sb + AS_Q + lrow * QROWB + lhalf * 128;
        const __half* gq = qb + (size_t)lrow * 128 + lhalf * 64;
        #pragma unroll
        for (int j = 0; j < 8; j++) cpa16(sq + j*16, gq + j*8);
        CPA_COMMIT();
    }

    const uint32_t kbuf[2] = { sb + AS_K0, sb + AS_K1 };
    const uint32_t vbuf[2] = { sb + AS_V0, sb + AS_V1 };

    const uint32_t aoffQ = sb + AS_Q + (uint32_t)(wm + (lane & 15)) * QROWB + (lane >> 4) * 16;
    const uint32_t boffK = (uint32_t)(((lane >> 4) & 1) * 8 + (lane & 7)) * KROWB
                         + ((lane >> 3) & 1) * 16;
    const uint32_t boffV = (uint32_t)(((lane >> 4) & 1) * 8 + (lane & 7)) * VROWB
                         + ((lane >> 3) & 1) * 16;

    const int r0 = lane >> 2;
    const int cql = (lane & 3) * 2;

    const uint32_t* mrow0 = mbits + ((size_t)b * SEQ + (q0g + wm + r0)) * (SEQ/32);
    const uint32_t* mrow1 = mrow0 + 8 * (SEQ/32);

    // stage one 64-key K/V block: K 64x256B, V 64x128B, 256 threads
    #define STAGE_KV(it, buf) do {                                                     \
        const int kb0_ = (it) * 64;                                                    \
        const int row_ = tid >> 2, qtr_ = tid & 3;                                     \
        const uint32_t sk = kbuf[buf] + row_ * KROWB + qtr_ * 64;                      \
        const __half* gk = kb + (size_t)(kb0_ + row_) * 128 + qtr_ * 32;               \
        cpa16(sk,      gk);                                                            \
        cpa16(sk + 16, gk + 8);                                                        \
        cpa16(sk + 32, gk + 16);                                                       \
        cpa16(sk + 48, gk + 24);                                                       \
        const uint32_t sv = vbuf[buf] + row_ * VROWB + qtr_ * 32;                      \
        const __half* gv = vb + (size_t)row_ * SEQ + kb0_ + qtr_ * 16;                 \
        cpa16(sv,      gv);                                                            \
        cpa16(sv + 16, gv + 8);                                                        \
        CPA_COMMIT();                                                                  \
    } while (0)

    STAGE_KV(0, 0);

    float o[8][4] = {};
    float m0 = -1e30f, m1 = -1e30f, l0 = 0.f, l1 = 0.f;

    for (int it = 0; it < SEQ/64; it++) {
        const int cur = it & 1;
        const int kb0 = it * 64;

        // prefetch mask words (independent LDG, overlaps staging wait)
        const uint2 mA = *(const uint2*)(mrow0 + (kb0 >> 5));
        const uint2 mB = *(const uint2*)(mrow1 + (kb0 >> 5));

        if (it + 1 < SEQ/64) { STAGE_KV(it + 1, cur ^ 1); CPA_WAIT(1); }
        else                 { CPA_WAIT(0); }
        __syncthreads();

        // ---- S = Q K^T (fp16 2-term, 128-dim, 64 keys) ----
        float s[8][4] = {};
        #pragma unroll
        for (int kk = 0; kk < 8; kk++) {
            uint32_t a0,a1,a2,a3;
            ldsm4(a0,a1,a2,a3, aoffQ + kk*32);
            #pragma unroll
            for (int np = 0; np < 4; np++) {
                uint32_t q0,q1,q2,q3;
                ldsm4(q0,q1,q2,q3, kbuf[cur] + boffK + (uint32_t)np * (16*KROWB) + kk*32);
                mma16816h(s[2*np][0], s[2*np][1], s[2*np][2], s[2*np][3], a0,a1,a2,a3, q0,q1);
                mma16816h(s[2*np+1][0], s[2*np+1][1], s[2*np+1][2], s[2*np+1][3], a0,a1,a2,a3, q2,q3);
            }
        }

        // ---- mask + scale (log2 units) + row max ----
        float mx0 = -1e30f, mx1 = -1e30f;
        #pragma unroll
        for (int t = 0; t < 8; t++) {
            const int sh = (t & 3) * 8 + cql;
            const uint32_t a = ((t < 4) ? mA.x : mA.y) >> sh;
            const uint32_t c = ((t < 4) ? mB.x : mB.y) >> sh;
            s[t][0] = (a & 1u) ? s[t][0] * LOG2E_8TH : -1e9f;
            s[t][1] = (a & 2u) ? s[t][1] * LOG2E_8TH : -1e9f;
            s[t][2] = (c & 1u) ? s[t][2] * LOG2E_8TH : -1e9f;
            s[t][3] = (c & 2u) ? s[t][3] * LOG2E_8TH : -1e9f;
            mx0 = fmaxf(mx0, fmaxf(s[t][0], s[t][1]));
            mx1 = fmaxf(mx1, fmaxf(s[t][2], s[t][3]));
        }
        mx0 = fmaxf(mx0, __shfl_xor_sync(0xffffffffu, mx0, 1));
        mx0 = fmaxf(mx0, __shfl_xor_sync(0xffffffffu, mx0, 2));
        mx1 = fmaxf(mx1, __shfl_xor_sync(0xffffffffu, mx1, 1));
        mx1 = fmaxf(mx1, __shfl_xor_sync(0xffffffffu, mx1, 2));

        const float nm0 = fmaxf(m0, mx0), nm1 = fmaxf(m1, mx1);
        const float c0 = exp2f(m0 - nm0), c1 = exp2f(m1 - nm1);
        m0 = nm0; m1 = nm1;

        // rescale O
        #pragma unroll
        for (int nt = 0; nt < 8; nt++) {
            o[nt][0] *= c0; o[nt][1] *= c0;
            o[nt][2] *= c1; o[nt][3] *= c1;
        }

        // ---- half-split: exp2 + fp16 hi/lo pack + PV (2 passes) ----
        float rs0 = 0.f, rs1 = 0.f;
        #pragma unroll
        for (int half = 0; half < 2; half++) {
            uint32_t php[4][2], plp[4][2];
            #pragma unroll
            for (int tt = 0; tt < 4; tt++) {
                const int t = half*4 + tt;
                float p0 = exp2f(s[t][0] - nm0);
                float p1 = exp2f(s[t][1] - nm0);
                float p2 = exp2f(s[t][2] - nm1);
                float p3 = exp2f(s[t][3] - nm1);
                rs0 += p0 + p1; rs1 += p2 + p3;
                __half h0 = __float2half_rn(p0), h1 = __float2half_rn(p1);
                __half h2 = __float2half_rn(p2), h3 = __float2half_rn(p3);
                __half2 ph0 = __halves2half2(h0, h1);
                __half2 ph1 = __halves2half2(h2, h3);
                php[tt][0] = *(uint32_t*)&ph0;
                php[tt][1] = *(uint32_t*)&ph1;
                __half2 pl0 = __floats2half2_rn(p0 - __half2float(h0),
                                                p1 - __half2float(h1));
                __half2 pl1 = __floats2half2_rn(p2 - __half2float(h2),
                                                p3 - __half2float(h3));
                plp[tt][0] = *(uint32_t*)&pl0;
                plp[tt][1] = *(uint32_t*)&pl1;
            }
            #pragma unroll
            for (int pass = 0; pass < 2; pass++) {
                #pragma unroll
                for (int jj = 0; jj < 2; jj++) {
                    const int j = half*2 + jj;
                    uint32_t a0, a1, a2, a3;
                    if (pass == 1) { a0 = plp[2*jj][0]; a1 = plp[2*jj][1]; a2 = plp[2*jj+1][0]; a3 = plp[2*jj+1][1]; }
                    else           { a0 = php[2*jj][0]; a1 = php[2*jj][1]; a2 = php[2*jj+1][0]; a3 = php[2*jj+1][1]; }
                    #pragma unroll
                    for (int np = 0; np < 4; np++) {
                        uint32_t q0,q1,q2,q3;
                        ldsm4(q0,q1,q2,q3, vbuf[cur] + boffV + (uint32_t)np * (16*VROWB) + j*32);
                        mma16816h(o[2*np][0], o[2*np][1], o[2*np][2], o[2*np][3], a0,a1,a2,a3, q0,q1);
                        mma16816h(o[2*np+1][0], o[2*np+1][1], o[2*np+1][2], o[2*np+1][3], a0,a1,a2,a3, q2,q3);
                    }
                }
            }
        }
        l0 = l0 * c0;
        l1 = l1 * c1;
        rs0 += __shfl_xor_sync(0xffffffffu, rs0, 1);
        rs0 += __shfl_xor_sync(0xffffffffu, rs0, 2);
        rs1 += __shfl_xor_sync(0xffffffffu, rs1, 1);
        rs1 += __shfl_xor_sync(0xffffffffu, rs1, 2);
        l0 += rs0;
        l1 += rs1;

        __syncthreads();   // all reads of buffer `cur` done before restaging
    }

    // ---- normalize & write fp16 ctx (Ch at [0,1024), Cl at [1024,2048)) ----
    const float i0 = 1.f / l0, i1 = 1.f / l1;
    const int row0 = q0g + wm + r0;
    __half* c0p = cb + ((size_t)b * SEQ + row0) * GK + h * DKH;
    __half* c1p = cb + ((size_t)b * SEQ + row0 + 8) * GK + h * DKH;
    #pragma unroll
    for (int nt = 0; nt < 8; nt++) {
        const int col = nt * 8 + cql;
        const float x0 = o[nt][0] * i0, y0 = o[nt][1] * i0;
        const float x1 = o[nt][2] * i1, y1 = o[nt][3] * i1;
        {
            __half hx = __float2half_rn(x0), hy = __float2half_rn(y0);
            *(__half2*)(c0p + col)        = __halves2half2(hx, hy);
            *(__half2*)(c0p + 1024 + col) = __floats2half2_rn(x0 - __half2float(hx),
                                                              y0 - __half2float(hy));
        }
        {
            __half hx = __float2half_rn(x1), hy = __float2half_rn(y1);
            *(__half2*)(c1p + col)        = __halves2half2(hx, hy);
            *(__half2*)(c1p + 1024 + col) = __floats2half2_rn(x1 - __half2float(hx),
                                                              y1 - __half2float(hy));
        }
    }
    #undef STAGE_KV
}

// ---------------------------------------------------------------------------
extern "C" void kernel_launch(void* const* d_in, const int* in_sizes, int n_in,
                              void* d_out, int out_size)
{
    (void)in_sizes; (void)n_in; (void)out_size;
    const float* hid  = (const float*)d_in[0];
    const int*   mask = (const int*)  d_in[1];
    const float* Wq   = (const float*)d_in[2];
    const float* bq   = (const float*)d_in[3];
    const float* Wk   = (const float*)d_in[4];
    const float* bk   = (const float*)d_in[5];
    const float* Wv   = (const float*)d_in[6];
    const float* bv   = (const float*)d_in[7];
    const float* Wo   = (const float*)d_in[8];
    const float* bo   = (const float*)d_in[9];
    float* out = (float*)d_out;

    uint4 *ab, *wb, *cb, *qs, *ks, *vt;
    float *vp;
    uint32_t* mbp;
    cudaGetSymbolAddress((void**)&ab, g_abig);
    cudaGetSymbolAddress((void**)&wb, g_wbig);
    cudaGetSymbolAddress((void**)&cb, g_cbig);
    cudaGetSymbolAddress((void**)&qs, g_qs);
    cudaGetSymbolAddress((void**)&ks, g_ks);
    cudaGetSymbolAddress((void**)&vt, g_vt);
    cudaGetSymbolAddress((void**)&vp, g_v);
    cudaGetSymbolAddress((void**)&mbp, g_mbits);

    const size_t WOFF = (size_t)DM * GK / 8;   // uint4 per fp16 weight matrix

    cudaFuncSetAttribute(attn_mma, cudaFuncAttributeMaxDynamicSharedMemorySize, ASMEM);

    mask_pack<<<(size_t)BATCH*SEQ*SEQ/256, 256>>>(mask, mbp);

    split_kernel<0><<<MTOT, 256>>>(hid, (__half*)ab);
    split_kernel<1><<<DM, 256>>>(Wq, (__half*)(wb + 0*WOFF));
    split_kernel<1><<<DM, 256>>>(Wk, (__half*)(wb + 1*WOFF));
    split_kernel<1><<<DM, 256>>>(Wv, (__half*)(wb + 2*WOFF));
    split_kernel<1><<<DM, 256>>>(Wo, (__half*)(wb + 3*WOFF));

    const dim3 gg(MTOT/128, DM/128);
    hgemm<1><<<gg, 256, HSMEM>>>((const __half*)ab, (const __half*)(wb + 0*WOFF), bq, qs);
    hgemm<2><<<gg, 256, HSMEM>>>((const __half*)ab, (const __half*)(wb + 1*WOFF), bk, ks);
    hgemm<0><<<gg, 256, HSMEM>>>((const __half*)ab, (const __half*)(wb + 2*WOFF), bv, vp);

    v_half<<<dim3(SEQ/128, BATCH*HEADS), 256>>>(vp, (__half*)vt);

    attn_mma<<<dim3(SEQ/128, BATCH*HEADS), 256, ASMEM>>>(
        (const __half*)qs, (const __half*)ks,
        (const __half*)vt, mbp, (__half*)cb);

    hgemm<0><<<gg, 256, HSMEM>>>((const __half*)cb, (const __half*)(wb + 3*WOFF), bo, out);
}